// round 7
// baseline (speedup 1.0000x reference)
#include <cuda_runtime.h>
#include <cuda_bf16.h>
#include <math.h>
#include <stdint.h>

using bf16 = __nv_bfloat16;

#define HIDDEN   2048
#define NHEADS   16
#define HDIM     128
#define BATCH    2
#define SEQ      2048
#define MTOT     (BATCH * SEQ)                         // 4096
#define OUT_ELEMS   ((size_t)MTOT * HIDDEN)            // 8388608
#define KV_ELEMS    ((size_t)MTOT * HDIM)              // 524288
#define CACHE_ELEMS ((size_t)BATCH * NHEADS * SEQ * HDIM)

// ---------------- scratch (__device__ globals; no allocation) ----------------
__device__ bf16 g_hsH[OUT_ELEMS], g_hsL[OUT_ELEMS];
__device__ bf16 g_WqH[(size_t)HIDDEN * HIDDEN], g_WqL[(size_t)HIDDEN * HIDDEN];
__device__ bf16 g_WkH[(size_t)HDIM * HIDDEN],  g_WkL[(size_t)HDIM * HIDDEN];
__device__ bf16 g_WvH[(size_t)HDIM * HIDDEN],  g_WvL[(size_t)HDIM * HIDDEN];
__device__ bf16 g_WoH[(size_t)HIDDEN * HIDDEN], g_WoL[(size_t)HIDDEN * HIDDEN];
__device__ bf16 g_QH[OUT_ELEMS], g_QL[OUT_ELEMS];
__device__ bf16 g_KH[KV_ELEMS], g_KL[KV_ELEMS];
__device__ bf16 g_VH[KV_ELEMS], g_VL[KV_ELEMS];
__device__ float g_Kf[KV_ELEMS], g_Vf[KV_ELEMS];
__device__ bf16 g_AH[OUT_ELEMS], g_AL[OUT_ELEMS];

// ---------------- low-level helpers ----------------
__device__ __forceinline__ uint32_t smem_u32(const void* p) {
    return (uint32_t)__cvta_generic_to_shared(p);
}
__device__ __forceinline__ void cp16(void* dst, const void* src) {
    asm volatile("cp.async.cg.shared.global [%0], [%1], 16;\n"
                 :: "r"(smem_u32(dst)), "l"(src));
}
__device__ __forceinline__ void cp_commit() { asm volatile("cp.async.commit_group;\n"); }
template<int N> __device__ __forceinline__ void cp_wait() {
    asm volatile("cp.async.wait_group %0;\n" :: "n"(N));
}
__device__ __forceinline__ void ldsm4(uint32_t& r0, uint32_t& r1, uint32_t& r2, uint32_t& r3,
                                      uint32_t addr) {
    asm volatile("ldmatrix.sync.aligned.m8n8.x4.shared.b16 {%0,%1,%2,%3},[%4];\n"
                 : "=r"(r0), "=r"(r1), "=r"(r2), "=r"(r3) : "r"(addr));
}
__device__ __forceinline__ void ldsm4t(uint32_t& r0, uint32_t& r1, uint32_t& r2, uint32_t& r3,
                                       uint32_t addr) {
    asm volatile("ldmatrix.sync.aligned.m8n8.x4.trans.shared.b16 {%0,%1,%2,%3},[%4];\n"
                 : "=r"(r0), "=r"(r1), "=r"(r2), "=r"(r3) : "r"(addr));
}
__device__ __forceinline__ void mma_bf16(float* c, uint32_t a0, uint32_t a1, uint32_t a2,
                                         uint32_t a3, uint32_t b0, uint32_t b1) {
    asm volatile(
        "mma.sync.aligned.m16n8k16.row.col.f32.bf16.bf16.f32 "
        "{%0,%1,%2,%3},{%4,%5,%6,%7},{%8,%9},{%0,%1,%2,%3};\n"
        : "+f"(c[0]), "+f"(c[1]), "+f"(c[2]), "+f"(c[3])
        : "r"(a0), "r"(a1), "r"(a2), "r"(a3), "r"(b0), "r"(b1));
}
__device__ __forceinline__ uint32_t bpack(float a, float b) {
    __nv_bfloat162 t;
    t.x = __float2bfloat16(a);
    t.y = __float2bfloat16(b);
    return *reinterpret_cast<uint32_t*>(&t);
}
__device__ __forceinline__ void split_store2(bf16* H, bf16* L, size_t idx, float x, float y) {
    float hx = __bfloat162float(__float2bfloat16(x));
    float hy = __bfloat162float(__float2bfloat16(y));
    uint32_t hh = bpack(hx, hy);
    uint32_t ll = bpack(x - hx, y - hy);
    *reinterpret_cast<uint32_t*>(H + idx) = hh;
    *reinterpret_cast<uint32_t*>(L + idx) = ll;
}

// ---------------- fused split: fp32 -> bf16 hi/lo, 5 tensors, one launch ----------------
__device__ __forceinline__ void split_one(const float* __restrict__ x,
                                          bf16* __restrict__ h, bf16* __restrict__ l,
                                          size_t i4) {
    size_t i = i4 * 4;
    float4 v = *reinterpret_cast<const float4*>(x + i);
    float h0 = __bfloat162float(__float2bfloat16(v.x));
    float h1 = __bfloat162float(__float2bfloat16(v.y));
    float h2 = __bfloat162float(__float2bfloat16(v.z));
    float h3 = __bfloat162float(__float2bfloat16(v.w));
    uint2 hp = make_uint2(bpack(h0, h1), bpack(h2, h3));
    uint2 lp = make_uint2(bpack(v.x - h0, v.y - h1), bpack(v.z - h2, v.w - h3));
    *reinterpret_cast<uint2*>(h + i) = hp;
    *reinterpret_cast<uint2*>(l + i) = lp;
}

#define N4_HS  ((size_t)OUT_ELEMS / 4)                 // 2097152
#define N4_WQ  ((size_t)HIDDEN * HIDDEN / 4)           // 1048576
#define N4_WK  ((size_t)HDIM * HIDDEN / 4)             // 65536
#define N4_ALL (N4_HS + 2 * N4_WQ + 2 * N4_WK)         // 4325376

__global__ __launch_bounds__(256) void split_all_kernel(
    const float* __restrict__ hs, bf16* __restrict__ hsH, bf16* __restrict__ hsL,
    const float* __restrict__ Wq, bf16* __restrict__ WqH, bf16* __restrict__ WqL,
    const float* __restrict__ Wk, bf16* __restrict__ WkH, bf16* __restrict__ WkL,
    const float* __restrict__ Wv, bf16* __restrict__ WvH, bf16* __restrict__ WvL,
    const float* __restrict__ Wo, bf16* __restrict__ WoH, bf16* __restrict__ WoL)
{
    size_t i = (size_t)blockIdx.x * blockDim.x + threadIdx.x;
    if (i >= N4_ALL) return;
    if (i < N4_HS) { split_one(hs, hsH, hsL, i); return; }
    i -= N4_HS;
    if (i < N4_WQ) { split_one(Wq, WqH, WqL, i); return; }
    i -= N4_WQ;
    if (i < N4_WK) { split_one(Wk, WkH, WkL, i); return; }
    i -= N4_WK;
    if (i < N4_WK) { split_one(Wv, WvH, WvL, i); return; }
    i -= N4_WK;
    split_one(Wo, WoH, WoL, i);
}

// =================================================================
// bf16x3 GEMM: C[M,N] = A[M,K] * W[N,K]^T  (acc = Ah*Wh + Ah*Wl + Al*Wh)
// 128x128x32 tile, 256 threads (8 warps, 2x4), warp tile 64x32.
// =================================================================
#define GBM 128
#define GBN 128
#define GBK 32
#define GSTR 40
#define GTILE (GBM * GSTR)
#define GEMM_SMEM (2 * 4 * GTILE * 2)

__global__ __launch_bounds__(256, 2) void gemm3_kernel(
    const bf16* __restrict__ Ah, const bf16* __restrict__ Al,
    const bf16* __restrict__ Wh0, const bf16* __restrict__ Wl0,
    float* __restrict__ Cf0, bf16* __restrict__ Ch0, bf16* __restrict__ Cl0,
    const bf16* __restrict__ Wh1, const bf16* __restrict__ Wl1,
    float* __restrict__ Cf1, bf16* __restrict__ Ch1, bf16* __restrict__ Cl1,
    int M, int N, int K)
{
    const bf16* Wh = Wh0; const bf16* Wl = Wl0;
    float* Cf = Cf0; bf16* Ch = Ch0; bf16* Cl = Cl0;
    if (blockIdx.z == 1) { Wh = Wh1; Wl = Wl1; Cf = Cf1; Ch = Ch1; Cl = Cl1; }

    extern __shared__ bf16 smg[];
    const int tid = threadIdx.x;
    const int lane = tid & 31;
    const int warp = tid >> 5;
    const int wm = (warp >> 2) * 64;
    const int wn = (warp & 3) * 32;
    const int bm = blockIdx.y * GBM;
    const int bn = blockIdx.x * GBN;

    float acc[4][4][4];
    #pragma unroll
    for (int a = 0; a < 4; a++)
        #pragma unroll
        for (int b = 0; b < 4; b++)
            #pragma unroll
            for (int c = 0; c < 4; c++) acc[a][b][c] = 0.f;

    const int T = K / GBK;

    auto load_stage = [&](int t, int buf) {
        bf16* base = smg + buf * (4 * GTILE);
        const int k0 = t * GBK;
        #pragma unroll
        for (int p = 0; p < 2; p++) {
            int q = tid + p * 256;
            int r = q >> 2;
            int c = (q & 3) * 8;
            size_t aoff = (size_t)(bm + r) * K + k0 + c;
            size_t woff = (size_t)(bn + r) * K + k0 + c;
            int soff = r * GSTR + c;
            cp16(base + soff,             Ah + aoff);
            cp16(base + GTILE + soff,     Al + aoff);
            cp16(base + 2 * GTILE + soff, Wh + woff);
            cp16(base + 3 * GTILE + soff, Wl + woff);
        }
    };

    load_stage(0, 0);
    cp_commit();

    const int arow = (lane & 15);
    const int acol = (lane >> 4) * 8;
    const int bnrow = (lane & 7) + ((lane & 16) ? 8 : 0);
    const int bkofs = (lane & 8) ? 8 : 0;

    for (int t = 0; t < T; t++) {
        if (t + 1 < T) { load_stage(t + 1, (t + 1) & 1); cp_commit(); cp_wait<1>(); }
        else           { cp_wait<0>(); }
        __syncthreads();

        bf16* base = smg + (t & 1) * (4 * GTILE);
        bf16* sAh = base;
        bf16* sAl = base + GTILE;
        bf16* sWh = base + 2 * GTILE;
        bf16* sWl = base + 3 * GTILE;

        #pragma unroll
        for (int kt = 0; kt < 2; kt++) {
            uint32_t ah[4][4], al[4][4];
            #pragma unroll
            for (int mt = 0; mt < 4; mt++) {
                uint32_t ad = smem_u32(sAh + (wm + mt * 16 + arow) * GSTR + kt * 16 + acol);
                ldsm4(ah[mt][0], ah[mt][1], ah[mt][2], ah[mt][3], ad);
                uint32_t ad2 = smem_u32(sAl + (wm + mt * 16 + arow) * GSTR + kt * 16 + acol);
                ldsm4(al[mt][0], al[mt][1], al[mt][2], al[mt][3], ad2);
            }
            #pragma unroll
            for (int np = 0; np < 2; np++) {
                uint32_t bh[4];
                uint32_t bd = smem_u32(sWh + (wn + np * 16 + bnrow) * GSTR + kt * 16 + bkofs);
                ldsm4(bh[0], bh[1], bh[2], bh[3], bd);
                #pragma unroll
                for (int mt = 0; mt < 4; mt++) {
                    mma_bf16(acc[mt][np * 2],     ah[mt][0], ah[mt][1], ah[mt][2], ah[mt][3], bh[0], bh[1]);
                    mma_bf16(acc[mt][np * 2 + 1], ah[mt][0], ah[mt][1], ah[mt][2], ah[mt][3], bh[2], bh[3]);
                    mma_bf16(acc[mt][np * 2],     al[mt][0], al[mt][1], al[mt][2], al[mt][3], bh[0], bh[1]);
                    mma_bf16(acc[mt][np * 2 + 1], al[mt][0], al[mt][1], al[mt][2], al[mt][3], bh[2], bh[3]);
                }
                uint32_t bl[4];
                uint32_t bd2 = smem_u32(sWl + (wn + np * 16 + bnrow) * GSTR + kt * 16 + bkofs);
                ldsm4(bl[0], bl[1], bl[2], bl[3], bd2);
                #pragma unroll
                for (int mt = 0; mt < 4; mt++) {
                    mma_bf16(acc[mt][np * 2],     ah[mt][0], ah[mt][1], ah[mt][2], ah[mt][3], bl[0], bl[1]);
                    mma_bf16(acc[mt][np * 2 + 1], ah[mt][0], ah[mt][1], ah[mt][2], ah[mt][3], bl[2], bl[3]);
                }
            }
        }
        __syncthreads();
    }

    const int gid = lane >> 2;
    const int tig = lane & 3;
    #pragma unroll
    for (int mt = 0; mt < 4; mt++) {
        int r0 = bm + wm + mt * 16 + gid;
        int r1 = r0 + 8;
        #pragma unroll
        for (int nt = 0; nt < 4; nt++) {
            int c = bn + wn + nt * 8 + tig * 2;
            float* a = acc[mt][nt];
            if (Cf) {
                *reinterpret_cast<float2*>(&Cf[(size_t)r0 * N + c]) = make_float2(a[0], a[1]);
                *reinterpret_cast<float2*>(&Cf[(size_t)r1 * N + c]) = make_float2(a[2], a[3]);
            }
            if (Ch) {
                split_store2(Ch, Cl, (size_t)r0 * N + c, a[0], a[1]);
                split_store2(Ch, Cl, (size_t)r1 * N + c, a[2], a[3]);
            }
        }
    }
}

// =================================================================
// Flash attention, bf16x3 mma, double-buffered K/V pipeline.
// CTA: 128 q rows, 256 threads (8 warps; warp owns 16 q rows, full d=128).
// 1 CTA/SM (smem ~209KB). K/V tile t+1 prefetched during compute of t.
// =================================================================
#define ABM 128
#define ABN 64
#define DSTR 136
#define QTILE (ABM * DSTR)          // 17408 b16 per Q array
#define KTILE (ABN * DSTR)          // 8704 b16 per KV array
#define ATTN_SMEM ((2 * QTILE + 8 * KTILE) * 2 + 2 * 64 * 4)   // 209408 B

__global__ __launch_bounds__(256, 1) void attn3_kernel(
    const bf16* __restrict__ Qh, const bf16* __restrict__ Ql,
    const bf16* __restrict__ Kh, const bf16* __restrict__ Kl,
    const bf16* __restrict__ Vh, const bf16* __restrict__ Vl,
    const float* __restrict__ mask,
    bf16* __restrict__ Oh, bf16* __restrict__ Ol)
{
    extern __shared__ bf16 sma[];
    bf16* sQh = sma;
    bf16* sQl = sma + QTILE;
    bf16* kvbase = sma + 2 * QTILE;                 // [buf][4][KTILE]
    float* sbias = reinterpret_cast<float*>(sma + 2 * QTILE + 8 * KTILE);  // [2][64] raw mask

    const int tid = threadIdx.x;
    const int lane = tid & 31;
    const int warp = tid >> 5;
    const int gid = lane >> 2;
    const int tig = lane & 3;
    const int b = blockIdx.z;
    const int h = blockIdx.y;
    const int q0 = blockIdx.x * ABM;
    const float scale = 0.08838834764831845f;   // 1/sqrt(128)

    auto load_kv = [&](int t, int buf) {
        bf16* kb = kvbase + buf * (4 * KTILE);
        const int k0 = t * ABN;
        #pragma unroll
        for (int p = 0; p < 4; p++) {
            int idx = tid + p * 256;
            int r = idx >> 4;
            int c = (idx & 15) * 8;
            size_t g = ((size_t)(b * SEQ + k0 + r)) * HDIM + c;
            int s = r * DSTR + c;
            cp16(kb + s,             Kh + g);
            cp16(kb + KTILE + s,     Kl + g);
            cp16(kb + 2 * KTILE + s, Vh + g);
            cp16(kb + 3 * KTILE + s, Vl + g);
        }
        if (tid < 16)
            cp16(&sbias[buf * 64 + tid * 4], mask + (size_t)b * SEQ + k0 + tid * 4);
    };

    // Q tile: 128 rows x 128 b16 (hi+lo)
    #pragma unroll
    for (int p = 0; p < 8; p++) {
        int idx = tid + p * 256;
        int r = idx >> 4;
        int c = (idx & 15) * 8;
        size_t g = ((size_t)(b * SEQ + q0 + r)) * HIDDEN + h * HDIM + c;
        cp16(sQh + r * DSTR + c, Qh + g);
        cp16(sQl + r * DSTR + c, Ql + g);
    }
    load_kv(0, 0);
    cp_commit();

    float o[16][4];
    #pragma unroll
    for (int i = 0; i < 16; i++)
        #pragma unroll
        for (int j = 0; j < 4; j++) o[i][j] = 0.f;
    float mrow0 = -1e30f, mrow1 = -1e30f;
    float lrow0 = 0.f, lrow1 = 0.f;

    const int arow = warp * 16 + (lane & 15);
    const int acol = (lane >> 4) * 8;
    const int bnrow = (lane & 7) + ((lane & 16) ? 8 : 0);
    const int bkofs = (lane & 8) ? 8 : 0;
    const int vrow = lane & 15;
    const int vd = (lane >> 4) * 8;

    const int T = SEQ / ABN;
    for (int t = 0; t < T; t++) {
        const int buf = t & 1;
        if (t + 1 < T) { load_kv(t + 1, buf ^ 1); cp_commit(); cp_wait<1>(); }
        else           { cp_wait<0>(); }
        __syncthreads();

        bf16* kb  = kvbase + buf * (4 * KTILE);
        bf16* sKh = kb;
        bf16* sKl = kb + KTILE;
        bf16* sVh = kb + 2 * KTILE;
        bf16* sVl = kb + 3 * KTILE;
        const float* bias = &sbias[buf * 64];

        // ---- S = Q K^T (bf16x3) ----
        float s[8][4];
        #pragma unroll
        for (int i = 0; i < 8; i++)
            #pragma unroll
            for (int j = 0; j < 4; j++) s[i][j] = 0.f;

        #pragma unroll
        for (int kt = 0; kt < 8; kt++) {
            uint32_t ah[4], al2[4];
            ldsm4(ah[0], ah[1], ah[2], ah[3],
                  smem_u32(sQh + arow * DSTR + kt * 16 + acol));
            ldsm4(al2[0], al2[1], al2[2], al2[3],
                  smem_u32(sQl + arow * DSTR + kt * 16 + acol));
            #pragma unroll
            for (int np = 0; np < 4; np++) {
                uint32_t bh[4];
                ldsm4(bh[0], bh[1], bh[2], bh[3],
                      smem_u32(sKh + (np * 16 + bnrow) * DSTR + kt * 16 + bkofs));
                mma_bf16(s[np * 2],     ah[0], ah[1], ah[2], ah[3], bh[0], bh[1]);
                mma_bf16(s[np * 2 + 1], ah[0], ah[1], ah[2], ah[3], bh[2], bh[3]);
                mma_bf16(s[np * 2],     al2[0], al2[1], al2[2], al2[3], bh[0], bh[1]);
                mma_bf16(s[np * 2 + 1], al2[0], al2[1], al2[2], al2[3], bh[2], bh[3]);
                uint32_t bl[4];
                ldsm4(bl[0], bl[1], bl[2], bl[3],
                      smem_u32(sKl + (np * 16 + bnrow) * DSTR + kt * 16 + bkofs));
                mma_bf16(s[np * 2],     ah[0], ah[1], ah[2], ah[3], bl[0], bl[1]);
                mma_bf16(s[np * 2 + 1], ah[0], ah[1], ah[2], ah[3], bl[2], bl[3]);
            }
        }

        // ---- online softmax ----
        float mn0 = mrow0, mn1 = mrow1;
        #pragma unroll
        for (int nt = 0; nt < 8; nt++) {
            int c = nt * 8 + tig * 2;
            float b0 = (1.0f - bias[c])     * -1e30f;
            float b1 = (1.0f - bias[c + 1]) * -1e30f;
            s[nt][0] = s[nt][0] * scale + b0;
            s[nt][1] = s[nt][1] * scale + b1;
            s[nt][2] = s[nt][2] * scale + b0;
            s[nt][3] = s[nt][3] * scale + b1;
            mn0 = fmaxf(mn0, fmaxf(s[nt][0], s[nt][1]));
            mn1 = fmaxf(mn1, fmaxf(s[nt][2], s[nt][3]));
        }
        mn0 = fmaxf(mn0, __shfl_xor_sync(0xffffffffu, mn0, 1));
        mn0 = fmaxf(mn0, __shfl_xor_sync(0xffffffffu, mn0, 2));
        mn1 = fmaxf(mn1, __shfl_xor_sync(0xffffffffu, mn1, 1));
        mn1 = fmaxf(mn1, __shfl_xor_sync(0xffffffffu, mn1, 2));
        float alpha0 = __expf(mrow0 - mn0);
        float alpha1 = __expf(mrow1 - mn1);
        mrow0 = mn0; mrow1 = mn1;

        float rs0 = 0.f, rs1 = 0.f;
        #pragma unroll
        for (int nt = 0; nt < 8; nt++) {
            s[nt][0] = __expf(s[nt][0] - mn0);
            s[nt][1] = __expf(s[nt][1] - mn0);
            s[nt][2] = __expf(s[nt][2] - mn1);
            s[nt][3] = __expf(s[nt][3] - mn1);
            rs0 += s[nt][0] + s[nt][1];
            rs1 += s[nt][2] + s[nt][3];
        }
        rs0 += __shfl_xor_sync(0xffffffffu, rs0, 1);
        rs0 += __shfl_xor_sync(0xffffffffu, rs0, 2);
        rs1 += __shfl_xor_sync(0xffffffffu, rs1, 1);
        rs1 += __shfl_xor_sync(0xffffffffu, rs1, 2);
        lrow0 = lrow0 * alpha0 + rs0;
        lrow1 = lrow1 * alpha1 + rs1;
        #pragma unroll
        for (int nt = 0; nt < 16; nt++) {
            o[nt][0] *= alpha0; o[nt][1] *= alpha0;
            o[nt][2] *= alpha1; o[nt][3] *= alpha1;
        }

        // ---- O += P V (bf16x3, P split in regs) ----
        #pragma unroll
        for (int t2 = 0; t2 < 4; t2++) {
            float* p0 = s[2 * t2];
            float* p1 = s[2 * t2 + 1];
            float h00 = __bfloat162float(__float2bfloat16(p0[0]));
            float h01 = __bfloat162float(__float2bfloat16(p0[1]));
            float h02 = __bfloat162float(__float2bfloat16(p0[2]));
            float h03 = __bfloat162float(__float2bfloat16(p0[3]));
            float h10 = __bfloat162float(__float2bfloat16(p1[0]));
            float h11 = __bfloat162float(__float2bfloat16(p1[1]));
            float h12 = __bfloat162float(__float2bfloat16(p1[2]));
            float h13 = __bfloat162float(__float2bfloat16(p1[3]));
            uint32_t pah[4] = { bpack(h00, h01), bpack(h02, h03), bpack(h10, h11), bpack(h12, h13) };
            uint32_t pal[4] = { bpack(p0[0] - h00, p0[1] - h01), bpack(p0[2] - h02, p0[3] - h03),
                                bpack(p1[0] - h10, p1[1] - h11), bpack(p1[2] - h12, p1[3] - h13) };
            #pragma unroll
            for (int dp = 0; dp < 8; dp++) {
                uint32_t bh[4];
                ldsm4t(bh[0], bh[1], bh[2], bh[3],
                       smem_u32(sVh + (t2 * 16 + vrow) * DSTR + dp * 16 + vd));
                mma_bf16(o[dp * 2],     pah[0], pah[1], pah[2], pah[3], bh[0], bh[1]);
                mma_bf16(o[dp * 2 + 1], pah[0], pah[1], pah[2], pah[3], bh[2], bh[3]);
                mma_bf16(o[dp * 2],     pal[0], pal[1], pal[2], pal[3], bh[0], bh[1]);
                mma_bf16(o[dp * 2 + 1], pal[0], pal[1], pal[2], pal[3], bh[2], bh[3]);
                uint32_t bl[4];
                ldsm4t(bl[0], bl[1], bl[2], bl[3],
                       smem_u32(sVl + (t2 * 16 + vrow) * DSTR + dp * 16 + vd));
                mma_bf16(o[dp * 2],     pah[0], pah[1], pah[2], pah[3], bl[0], bl[1]);
                mma_bf16(o[dp * 2 + 1], pah[0], pah[1], pah[2], pah[3], bl[2], bl[3]);
            }
        }
        __syncthreads();
    }

    // ---- epilogue: normalize, split, store in [B,S,H*D] ----
    float inv0 = 1.f / lrow0;
    float inv1 = 1.f / lrow1;
    int r0 = q0 + warp * 16 + gid;
    int r1 = r0 + 8;
    #pragma unroll
    for (int nt = 0; nt < 16; nt++) {
        int c = h * HDIM + nt * 8 + tig * 2;
        size_t i0 = (size_t)(b * SEQ + r0) * HIDDEN + c;
        size_t i1 = (size_t)(b * SEQ + r1) * HIDDEN + c;
        split_store2(Oh, Ol, i0, o[nt][0] * inv0, o[nt][1] * inv0);
        split_store2(Oh, Ol, i1, o[nt][2] * inv1, o[nt][3] * inv1);
    }
}

// =================================================================
// Broadcast single-KV-head K,V to [B,H,S,D] cache outputs
// =================================================================
__global__ __launch_bounds__(256) void bcast_kv_kernel(
    const float* __restrict__ K, const float* __restrict__ V,
    float* __restrict__ kout, float* __restrict__ vout)
{
    size_t idx = (size_t)blockIdx.x * blockDim.x + threadIdx.x;
    size_t total = KV_ELEMS;
    if (idx >= total) return;
    int b = (int)(idx / ((size_t)SEQ * HDIM));
    size_t rem = idx - (size_t)b * SEQ * HDIM;
    float kv = K[idx];
    float vv = V[idx];
    #pragma unroll
    for (int hh = 0; hh < NHEADS; hh++) {
        size_t oidx = ((size_t)b * NHEADS + hh) * SEQ * HDIM + rem;
        kout[oidx] = kv;
        vout[oidx] = vv;
    }
}

// =================================================================
extern "C" void kernel_launch(void* const* d_in, const int* in_sizes, int n_in,
                              void* d_out, int out_size) {
    const float* hs   = (const float*)d_in[0];
    const float* mask = (const float*)d_in[1];
    const float* Wq   = (const float*)d_in[2];
    const float* Wk   = (const float*)d_in[3];
    const float* Wv   = (const float*)d_in[4];
    const float* Wo   = (const float*)d_in[5];
    float* out = (float*)d_out;

    bf16 *hsH, *hsL, *WqH, *WqL, *WkH, *WkL, *WvH, *WvL, *WoH, *WoL;
    bf16 *QH, *QL, *KH, *KL, *VH, *VL, *AH, *AL;
    float *Kf, *Vf;
    cudaGetSymbolAddress((void**)&hsH, g_hsH); cudaGetSymbolAddress((void**)&hsL, g_hsL);
    cudaGetSymbolAddress((void**)&WqH, g_WqH); cudaGetSymbolAddress((void**)&WqL, g_WqL);
    cudaGetSymbolAddress((void**)&WkH, g_WkH); cudaGetSymbolAddress((void**)&WkL, g_WkL);
    cudaGetSymbolAddress((void**)&WvH, g_WvH); cudaGetSymbolAddress((void**)&WvL, g_WvL);
    cudaGetSymbolAddress((void**)&WoH, g_WoH); cudaGetSymbolAddress((void**)&WoL, g_WoL);
    cudaGetSymbolAddress((void**)&QH, g_QH);   cudaGetSymbolAddress((void**)&QL, g_QL);
    cudaGetSymbolAddress((void**)&KH, g_KH);   cudaGetSymbolAddress((void**)&KL, g_KL);
    cudaGetSymbolAddress((void**)&VH, g_VH);   cudaGetSymbolAddress((void**)&VL, g_VL);
    cudaGetSymbolAddress((void**)&AH, g_AH);   cudaGetSymbolAddress((void**)&AL, g_AL);
    cudaGetSymbolAddress((void**)&Kf, g_Kf);   cudaGetSymbolAddress((void**)&Vf, g_Vf);

    cudaFuncSetAttribute(gemm3_kernel, cudaFuncAttributeMaxDynamicSharedMemorySize, GEMM_SMEM);
    cudaFuncSetAttribute(attn3_kernel, cudaFuncAttributeMaxDynamicSharedMemorySize, ATTN_SMEM);

    // fused split of all inputs into bf16 hi/lo
    split_all_kernel<<<(unsigned)((N4_ALL + 255) / 256), 256>>>(
        hs, hsH, hsL, Wq, WqH, WqL, Wk, WkH, WkL, Wv, WvH, WvL, Wo, WoH, WoL);

    // Q projection: hi/lo out only
    gemm3_kernel<<<dim3(HIDDEN / GBN, MTOT / GBM, 1), 256, GEMM_SMEM>>>(
        hsH, hsL, WqH, WqL, nullptr, QH, QL,
        nullptr, nullptr, nullptr, nullptr, nullptr, MTOT, HIDDEN, HIDDEN);

    // K and V projections fused via blockIdx.z (fp32 for cache + hi/lo for attn)
    gemm3_kernel<<<dim3(HDIM / GBN, MTOT / GBM, 2), 256, GEMM_SMEM>>>(
        hsH, hsL, WkH, WkL, Kf, KH, KL,
        WvH, WvL, Vf, VH, VL, MTOT, HDIM, HIDDEN);

    // KV cache outputs
    if ((size_t)out_size >= OUT_ELEMS + 2 * CACHE_ELEMS) {
        bcast_kv_kernel<<<(unsigned)((KV_ELEMS + 255) / 256), 256>>>(
            Kf, Vf, out + OUT_ELEMS, out + OUT_ELEMS + CACHE_ELEMS);
    }

    // flash attention -> A (hi/lo)
    attn3_kernel<<<dim3(SEQ / ABM, NHEADS, BATCH), 256, ATTN_SMEM>>>(
        QH, QL, KH, KL, VH, VL, mask, AH, AL);

    // output projection -> fp32 out
    gemm3_kernel<<<dim3(HIDDEN / GBN, MTOT / GBM, 1), 256, GEMM_SMEM>>>(
        AH, AL, WoH, WoL, out, nullptr, nullptr,
        nullptr, nullptr, nullptr, nullptr, nullptr, MTOT, HIDDEN, HIDDEN);
}

// round 11
// speedup vs baseline: 1.5118x; 1.5118x over previous
#include <cuda_runtime.h>
#include <cuda_bf16.h>
#include <math.h>
#include <stdint.h>

using bf16 = __nv_bfloat16;

#define HIDDEN   2048
#define NHEADS   16
#define HDIM     128
#define BATCH    2
#define SEQ      2048
#define MTOT     (BATCH * SEQ)                         // 4096
#define OUT_ELEMS   ((size_t)MTOT * HIDDEN)            // 8388608
#define KV_ELEMS    ((size_t)MTOT * HDIM)              // 524288
#define CACHE_ELEMS ((size_t)BATCH * NHEADS * SEQ * HDIM)

// ---------------- scratch (__device__ globals; no allocation) ----------------
__device__ bf16 g_hsH[OUT_ELEMS], g_hsL[OUT_ELEMS];
__device__ bf16 g_WqH[(size_t)HIDDEN * HIDDEN], g_WqL[(size_t)HIDDEN * HIDDEN];
__device__ bf16 g_WkH[(size_t)HDIM * HIDDEN],  g_WkL[(size_t)HDIM * HIDDEN];
__device__ bf16 g_WvH[(size_t)HDIM * HIDDEN],  g_WvL[(size_t)HDIM * HIDDEN];
__device__ bf16 g_WoH[(size_t)HIDDEN * HIDDEN], g_WoL[(size_t)HIDDEN * HIDDEN];
__device__ bf16 g_QH[OUT_ELEMS], g_QL[OUT_ELEMS];
__device__ bf16 g_KH[KV_ELEMS], g_KL[KV_ELEMS];
__device__ bf16 g_VH[KV_ELEMS], g_VL[KV_ELEMS];
__device__ float g_Kf[KV_ELEMS], g_Vf[KV_ELEMS];
__device__ bf16 g_AH[OUT_ELEMS], g_AL[OUT_ELEMS];

// ---------------- low-level helpers ----------------
__device__ __forceinline__ uint32_t smem_u32(const void* p) {
    return (uint32_t)__cvta_generic_to_shared(p);
}
__device__ __forceinline__ void cp16(void* dst, const void* src) {
    asm volatile("cp.async.cg.shared.global [%0], [%1], 16;\n"
                 :: "r"(smem_u32(dst)), "l"(src));
}
__device__ __forceinline__ void cp_commit() { asm volatile("cp.async.commit_group;\n"); }
template<int N> __device__ __forceinline__ void cp_wait() {
    asm volatile("cp.async.wait_group %0;\n" :: "n"(N));
}
__device__ __forceinline__ void ldsm4(uint32_t& r0, uint32_t& r1, uint32_t& r2, uint32_t& r3,
                                      uint32_t addr) {
    asm volatile("ldmatrix.sync.aligned.m8n8.x4.shared.b16 {%0,%1,%2,%3},[%4];\n"
                 : "=r"(r0), "=r"(r1), "=r"(r2), "=r"(r3) : "r"(addr));
}
__device__ __forceinline__ void ldsm4t(uint32_t& r0, uint32_t& r1, uint32_t& r2, uint32_t& r3,
                                       uint32_t addr) {
    asm volatile("ldmatrix.sync.aligned.m8n8.x4.trans.shared.b16 {%0,%1,%2,%3},[%4];\n"
                 : "=r"(r0), "=r"(r1), "=r"(r2), "=r"(r3) : "r"(addr));
}
__device__ __forceinline__ void mma_bf16(float* c, uint32_t a0, uint32_t a1, uint32_t a2,
                                         uint32_t a3, uint32_t b0, uint32_t b1) {
    asm volatile(
        "mma.sync.aligned.m16n8k16.row.col.f32.bf16.bf16.f32 "
        "{%0,%1,%2,%3},{%4,%5,%6,%7},{%8,%9},{%0,%1,%2,%3};\n"
        : "+f"(c[0]), "+f"(c[1]), "+f"(c[2]), "+f"(c[3])
        : "r"(a0), "r"(a1), "r"(a2), "r"(a3), "r"(b0), "r"(b1));
}
__device__ __forceinline__ uint32_t bpack(float a, float b) {
    __nv_bfloat162 t;
    t.x = __float2bfloat16(a);
    t.y = __float2bfloat16(b);
    return *reinterpret_cast<uint32_t*>(&t);
}
__device__ __forceinline__ void split_store2(bf16* H, bf16* L, size_t idx, float x, float y) {
    float hx = __bfloat162float(__float2bfloat16(x));
    float hy = __bfloat162float(__float2bfloat16(y));
    uint32_t hh = bpack(hx, hy);
    uint32_t ll = bpack(x - hx, y - hy);
    *reinterpret_cast<uint32_t*>(H + idx) = hh;
    *reinterpret_cast<uint32_t*>(L + idx) = ll;
}

// ---------------- fused split: fp32 -> bf16 hi/lo, 5 tensors, one launch ----------------
__device__ __forceinline__ void split_one(const float* __restrict__ x,
                                          bf16* __restrict__ h, bf16* __restrict__ l,
                                          size_t i4) {
    size_t i = i4 * 4;
    float4 v = *reinterpret_cast<const float4*>(x + i);
    float h0 = __bfloat162float(__float2bfloat16(v.x));
    float h1 = __bfloat162float(__float2bfloat16(v.y));
    float h2 = __bfloat162float(__float2bfloat16(v.z));
    float h3 = __bfloat162float(__float2bfloat16(v.w));
    uint2 hp = make_uint2(bpack(h0, h1), bpack(h2, h3));
    uint2 lp = make_uint2(bpack(v.x - h0, v.y - h1), bpack(v.z - h2, v.w - h3));
    *reinterpret_cast<uint2*>(h + i) = hp;
    *reinterpret_cast<uint2*>(l + i) = lp;
}

#define N4_HS  ((size_t)OUT_ELEMS / 4)                 // 2097152
#define N4_WQ  ((size_t)HIDDEN * HIDDEN / 4)           // 1048576
#define N4_WK  ((size_t)HDIM * HIDDEN / 4)             // 65536
#define N4_ALL (N4_HS + 2 * N4_WQ + 2 * N4_WK)         // 4325376

__global__ __launch_bounds__(256) void split_all_kernel(
    const float* __restrict__ hs, bf16* __restrict__ hsH, bf16* __restrict__ hsL,
    const float* __restrict__ Wq, bf16* __restrict__ WqH, bf16* __restrict__ WqL,
    const float* __restrict__ Wk, bf16* __restrict__ WkH, bf16* __restrict__ WkL,
    const float* __restrict__ Wv, bf16* __restrict__ WvH, bf16* __restrict__ WvL,
    const float* __restrict__ Wo, bf16* __restrict__ WoH, bf16* __restrict__ WoL)
{
    size_t i = (size_t)blockIdx.x * blockDim.x + threadIdx.x;
    if (i >= N4_ALL) return;
    if (i < N4_HS) { split_one(hs, hsH, hsL, i); return; }
    i -= N4_HS;
    if (i < N4_WQ) { split_one(Wq, WqH, WqL, i); return; }
    i -= N4_WQ;
    if (i < N4_WK) { split_one(Wk, WkH, WkL, i); return; }
    i -= N4_WK;
    if (i < N4_WK) { split_one(Wv, WvH, WvL, i); return; }
    i -= N4_WK;
    split_one(Wo, WoH, WoL, i);
}

// =================================================================
// bf16x3 GEMM: C[M,N] = A[M,K] * W[N,K]^T  (acc = Ah*Wh + Ah*Wl + Al*Wh)
// 128x128x32 tile, 256 threads (8 warps, 2x4), warp tile 64x32.
// =================================================================
#define GBM 128
#define GBN 128
#define GBK 32
#define GSTR 40
#define GTILE (GBM * GSTR)
#define GEMM_SMEM (2 * 4 * GTILE * 2)

__global__ __launch_bounds__(256, 2) void gemm3_kernel(
    const bf16* __restrict__ Ah, const bf16* __restrict__ Al,
    const bf16* __restrict__ Wh0, const bf16* __restrict__ Wl0,
    float* __restrict__ Cf0, bf16* __restrict__ Ch0, bf16* __restrict__ Cl0,
    const bf16* __restrict__ Wh1, const bf16* __restrict__ Wl1,
    float* __restrict__ Cf1, bf16* __restrict__ Ch1, bf16* __restrict__ Cl1,
    int M, int N, int K)
{
    const bf16* Wh = Wh0; const bf16* Wl = Wl0;
    float* Cf = Cf0; bf16* Ch = Ch0; bf16* Cl = Cl0;
    if (blockIdx.z == 1) { Wh = Wh1; Wl = Wl1; Cf = Cf1; Ch = Ch1; Cl = Cl1; }

    extern __shared__ bf16 smg[];
    const int tid = threadIdx.x;
    const int lane = tid & 31;
    const int warp = tid >> 5;
    const int wm = (warp >> 2) * 64;
    const int wn = (warp & 3) * 32;
    const int bm = blockIdx.y * GBM;
    const int bn = blockIdx.x * GBN;

    float acc[4][4][4];
    #pragma unroll
    for (int a = 0; a < 4; a++)
        #pragma unroll
        for (int b = 0; b < 4; b++)
            #pragma unroll
            for (int c = 0; c < 4; c++) acc[a][b][c] = 0.f;

    const int T = K / GBK;

    auto load_stage = [&](int t, int buf) {
        bf16* base = smg + buf * (4 * GTILE);
        const int k0 = t * GBK;
        #pragma unroll
        for (int p = 0; p < 2; p++) {
            int q = tid + p * 256;
            int r = q >> 2;
            int c = (q & 3) * 8;
            size_t aoff = (size_t)(bm + r) * K + k0 + c;
            size_t woff = (size_t)(bn + r) * K + k0 + c;
            int soff = r * GSTR + c;
            cp16(base + soff,             Ah + aoff);
            cp16(base + GTILE + soff,     Al + aoff);
            cp16(base + 2 * GTILE + soff, Wh + woff);
            cp16(base + 3 * GTILE + soff, Wl + woff);
        }
    };

    load_stage(0, 0);
    cp_commit();

    const int arow = (lane & 15);
    const int acol = (lane >> 4) * 8;
    const int bnrow = (lane & 7) + ((lane & 16) ? 8 : 0);
    const int bkofs = (lane & 8) ? 8 : 0;

    for (int t = 0; t < T; t++) {
        if (t + 1 < T) { load_stage(t + 1, (t + 1) & 1); cp_commit(); cp_wait<1>(); }
        else           { cp_wait<0>(); }
        __syncthreads();

        bf16* base = smg + (t & 1) * (4 * GTILE);
        bf16* sAh = base;
        bf16* sAl = base + GTILE;
        bf16* sWh = base + 2 * GTILE;
        bf16* sWl = base + 3 * GTILE;

        #pragma unroll
        for (int kt = 0; kt < 2; kt++) {
            uint32_t ah[4][4], al[4][4];
            #pragma unroll
            for (int mt = 0; mt < 4; mt++) {
                uint32_t ad = smem_u32(sAh + (wm + mt * 16 + arow) * GSTR + kt * 16 + acol);
                ldsm4(ah[mt][0], ah[mt][1], ah[mt][2], ah[mt][3], ad);
                uint32_t ad2 = smem_u32(sAl + (wm + mt * 16 + arow) * GSTR + kt * 16 + acol);
                ldsm4(al[mt][0], al[mt][1], al[mt][2], al[mt][3], ad2);
            }
            #pragma unroll
            for (int np = 0; np < 2; np++) {
                uint32_t bh[4];
                uint32_t bd = smem_u32(sWh + (wn + np * 16 + bnrow) * GSTR + kt * 16 + bkofs);
                ldsm4(bh[0], bh[1], bh[2], bh[3], bd);
                #pragma unroll
                for (int mt = 0; mt < 4; mt++) {
                    mma_bf16(acc[mt][np * 2],     ah[mt][0], ah[mt][1], ah[mt][2], ah[mt][3], bh[0], bh[1]);
                    mma_bf16(acc[mt][np * 2 + 1], ah[mt][0], ah[mt][1], ah[mt][2], ah[mt][3], bh[2], bh[3]);
                    mma_bf16(acc[mt][np * 2],     al[mt][0], al[mt][1], al[mt][2], al[mt][3], bh[0], bh[1]);
                    mma_bf16(acc[mt][np * 2 + 1], al[mt][0], al[mt][1], al[mt][2], al[mt][3], bh[2], bh[3]);
                }
                uint32_t bl[4];
                uint32_t bd2 = smem_u32(sWl + (wn + np * 16 + bnrow) * GSTR + kt * 16 + bkofs);
                ldsm4(bl[0], bl[1], bl[2], bl[3], bd2);
                #pragma unroll
                for (int mt = 0; mt < 4; mt++) {
                    mma_bf16(acc[mt][np * 2],     ah[mt][0], ah[mt][1], ah[mt][2], ah[mt][3], bl[0], bl[1]);
                    mma_bf16(acc[mt][np * 2 + 1], ah[mt][0], ah[mt][1], ah[mt][2], ah[mt][3], bl[2], bl[3]);
                }
            }
        }
        __syncthreads();
    }

    const int gid = lane >> 2;
    const int tig = lane & 3;
    #pragma unroll
    for (int mt = 0; mt < 4; mt++) {
        int r0 = bm + wm + mt * 16 + gid;
        int r1 = r0 + 8;
        #pragma unroll
        for (int nt = 0; nt < 4; nt++) {
            int c = bn + wn + nt * 8 + tig * 2;
            float* a = acc[mt][nt];
            if (Cf) {
                *reinterpret_cast<float2*>(&Cf[(size_t)r0 * N + c]) = make_float2(a[0], a[1]);
                *reinterpret_cast<float2*>(&Cf[(size_t)r1 * N + c]) = make_float2(a[2], a[3]);
            }
            if (Ch) {
                split_store2(Ch, Cl, (size_t)r0 * N + c, a[0], a[1]);
                split_store2(Ch, Cl, (size_t)r1 * N + c, a[2], a[3]);
            }
        }
    }
}

// =================================================================
// Flash attention with bf16x3 mma.  (R6 winning configuration)
// CTA: 64 q rows, 128 threads (4 warps; warp owns 16 q rows, full d=128).
// Streams 64-key tiles; S/P/O in register fragments; P split hi/lo in regs.
// =================================================================
#define ABM 64
#define ABN 64
#define DSTR 136
#define ATILE (ABM * DSTR)                       // b16 per array
#define ATTN_SMEM (6 * ATILE * 2 + 256)          // bytes

__global__ __launch_bounds__(128, 2) void attn3_kernel(
    const bf16* __restrict__ Qh, const bf16* __restrict__ Ql,
    const bf16* __restrict__ Kh, const bf16* __restrict__ Kl,
    const bf16* __restrict__ Vh, const bf16* __restrict__ Vl,
    const float* __restrict__ mask,
    bf16* __restrict__ Oh, bf16* __restrict__ Ol)
{
    extern __shared__ bf16 sma[];
    bf16* sQh = sma;
    bf16* sQl = sma + ATILE;
    bf16* sKh = sma + 2 * ATILE;
    bf16* sKl = sma + 3 * ATILE;
    bf16* sVh = sma + 4 * ATILE;
    bf16* sVl = sma + 5 * ATILE;
    float* sbias = reinterpret_cast<float*>(sma + 6 * ATILE);

    const int tid = threadIdx.x;
    const int lane = tid & 31;
    const int warp = tid >> 5;
    const int gid = lane >> 2;
    const int tig = lane & 3;
    const int b = blockIdx.z;
    const int h = blockIdx.y;
    const int q0 = blockIdx.x * ABM;
    const float scale = 0.08838834764831845f;   // 1/sqrt(128)

    // Q tile: 64 rows x 128 b16 (hi+lo)
    #pragma unroll
    for (int p = 0; p < 8; p++) {
        int idx = tid + p * 128;
        int r = idx >> 4;
        int c = (idx & 15) * 8;
        size_t g = ((size_t)(b * SEQ + q0 + r)) * HIDDEN + h * HDIM + c;
        cp16(sQh + r * DSTR + c, Qh + g);
        cp16(sQl + r * DSTR + c, Ql + g);
    }
    cp_commit();

    float o[16][4];
    #pragma unroll
    for (int i = 0; i < 16; i++)
        #pragma unroll
        for (int j = 0; j < 4; j++) o[i][j] = 0.f;
    float mrow0 = -1e30f, mrow1 = -1e30f;
    float lrow0 = 0.f, lrow1 = 0.f;

    const int arow = warp * 16 + (lane & 15);
    const int acol = (lane >> 4) * 8;
    const int bnrow = (lane & 7) + ((lane & 16) ? 8 : 0);
    const int bkofs = (lane & 8) ? 8 : 0;
    const int vrow = lane & 15;
    const int vd = (lane >> 4) * 8;

    for (int k0 = 0; k0 < SEQ; k0 += ABN) {
        __syncthreads();
        #pragma unroll
        for (int p = 0; p < 8; p++) {
            int idx = tid + p * 128;
            int r = idx >> 4;
            int c = (idx & 15) * 8;
            size_t g = ((size_t)(b * SEQ + k0 + r)) * HDIM + c;
            int s = r * DSTR + c;
            cp16(sKh + s, Kh + g);
            cp16(sKl + s, Kl + g);
            cp16(sVh + s, Vh + g);
            cp16(sVl + s, Vl + g);
        }
        if (tid < ABN) sbias[tid] = (1.0f - mask[(size_t)b * SEQ + k0 + tid]) * -1e30f;
        cp_commit();
        cp_wait<0>();
        __syncthreads();

        // ---- S = Q K^T (bf16x3) ----
        float s[8][4];
        #pragma unroll
        for (int i = 0; i < 8; i++)
            #pragma unroll
            for (int j = 0; j < 4; j++) s[i][j] = 0.f;

        #pragma unroll
        for (int kt = 0; kt < 8; kt++) {
            uint32_t ah[4], al2[4];
            ldsm4(ah[0], ah[1], ah[2], ah[3],
                  smem_u32(sQh + arow * DSTR + kt * 16 + acol));
            ldsm4(al2[0], al2[1], al2[2], al2[3],
                  smem_u32(sQl + arow * DSTR + kt * 16 + acol));
            #pragma unroll
            for (int np = 0; np < 4; np++) {
                uint32_t bh[4];
                ldsm4(bh[0], bh[1], bh[2], bh[3],
                      smem_u32(sKh + (np * 16 + bnrow) * DSTR + kt * 16 + bkofs));
                mma_bf16(s[np * 2],     ah[0], ah[1], ah[2], ah[3], bh[0], bh[1]);
                mma_bf16(s[np * 2 + 1], ah[0], ah[1], ah[2], ah[3], bh[2], bh[3]);
                mma_bf16(s[np * 2],     al2[0], al2[1], al2[2], al2[3], bh[0], bh[1]);
                mma_bf16(s[np * 2 + 1], al2[0], al2[1], al2[2], al2[3], bh[2], bh[3]);
                uint32_t bl[4];
                ldsm4(bl[0], bl[1], bl[2], bl[3],
                      smem_u32(sKl + (np * 16 + bnrow) * DSTR + kt * 16 + bkofs));
                mma_bf16(s[np * 2],     ah[0], ah[1], ah[2], ah[3], bl[0], bl[1]);
                mma_bf16(s[np * 2 + 1], ah[0], ah[1], ah[2], ah[3], bl[2], bl[3]);
            }
        }

        // ---- online softmax (rows gid and gid+8 of this warp's 16) ----
        float mn0 = mrow0, mn1 = mrow1;
        #pragma unroll
        for (int nt = 0; nt < 8; nt++) {
            int c = nt * 8 + tig * 2;
            float b0 = sbias[c], b1 = sbias[c + 1];
            s[nt][0] = s[nt][0] * scale + b0;
            s[nt][1] = s[nt][1] * scale + b1;
            s[nt][2] = s[nt][2] * scale + b0;
            s[nt][3] = s[nt][3] * scale + b1;
            mn0 = fmaxf(mn0, fmaxf(s[nt][0], s[nt][1]));
            mn1 = fmaxf(mn1, fmaxf(s[nt][2], s[nt][3]));
        }
        mn0 = fmaxf(mn0, __shfl_xor_sync(0xffffffffu, mn0, 1));
        mn0 = fmaxf(mn0, __shfl_xor_sync(0xffffffffu, mn0, 2));
        mn1 = fmaxf(mn1, __shfl_xor_sync(0xffffffffu, mn1, 1));
        mn1 = fmaxf(mn1, __shfl_xor_sync(0xffffffffu, mn1, 2));
        float alpha0 = __expf(mrow0 - mn0);
        float alpha1 = __expf(mrow1 - mn1);
        mrow0 = mn0; mrow1 = mn1;

        float rs0 = 0.f, rs1 = 0.f;
        #pragma unroll
        for (int nt = 0; nt < 8; nt++) {
            s[nt][0] = __expf(s[nt][0] - mn0);
            s[nt][1] = __expf(s[nt][1] - mn0);
            s[nt][2] = __expf(s[nt][2] - mn1);
            s[nt][3] = __expf(s[nt][3] - mn1);
            rs0 += s[nt][0] + s[nt][1];
            rs1 += s[nt][2] + s[nt][3];
        }
        rs0 += __shfl_xor_sync(0xffffffffu, rs0, 1);
        rs0 += __shfl_xor_sync(0xffffffffu, rs0, 2);
        rs1 += __shfl_xor_sync(0xffffffffu, rs1, 1);
        rs1 += __shfl_xor_sync(0xffffffffu, rs1, 2);
        lrow0 = lrow0 * alpha0 + rs0;
        lrow1 = lrow1 * alpha1 + rs1;
        #pragma unroll
        for (int nt = 0; nt < 16; nt++) {
            o[nt][0] *= alpha0; o[nt][1] *= alpha0;
            o[nt][2] *= alpha1; o[nt][3] *= alpha1;
        }

        // ---- O += P V (bf16x3, P split in regs) ----
        #pragma unroll
        for (int t2 = 0; t2 < 4; t2++) {
            float* p0 = s[2 * t2];
            float* p1 = s[2 * t2 + 1];
            float h00 = __bfloat162float(__float2bfloat16(p0[0]));
            float h01 = __bfloat162float(__float2bfloat16(p0[1]));
            float h02 = __bfloat162float(__float2bfloat16(p0[2]));
            float h03 = __bfloat162float(__float2bfloat16(p0[3]));
            float h10 = __bfloat162float(__float2bfloat16(p1[0]));
            float h11 = __bfloat162float(__float2bfloat16(p1[1]));
            float h12 = __bfloat162float(__float2bfloat16(p1[2]));
            float h13 = __bfloat162float(__float2bfloat16(p1[3]));
            uint32_t pah[4] = { bpack(h00, h01), bpack(h02, h03), bpack(h10, h11), bpack(h12, h13) };
            uint32_t pal[4] = { bpack(p0[0] - h00, p0[1] - h01), bpack(p0[2] - h02, p0[3] - h03),
                                bpack(p1[0] - h10, p1[1] - h11), bpack(p1[2] - h12, p1[3] - h13) };
            #pragma unroll
            for (int dp = 0; dp < 8; dp++) {
                uint32_t bh[4];
                ldsm4t(bh[0], bh[1], bh[2], bh[3],
                       smem_u32(sVh + (t2 * 16 + vrow) * DSTR + dp * 16 + vd));
                mma_bf16(o[dp * 2],     pah[0], pah[1], pah[2], pah[3], bh[0], bh[1]);
                mma_bf16(o[dp * 2 + 1], pah[0], pah[1], pah[2], pah[3], bh[2], bh[3]);
                mma_bf16(o[dp * 2],     pal[0], pal[1], pal[2], pal[3], bh[0], bh[1]);
                mma_bf16(o[dp * 2 + 1], pal[0], pal[1], pal[2], pal[3], bh[2], bh[3]);
                uint32_t bl[4];
                ldsm4t(bl[0], bl[1], bl[2], bl[3],
                       smem_u32(sVl + (t2 * 16 + vrow) * DSTR + dp * 16 + vd));
                mma_bf16(o[dp * 2],     pah[0], pah[1], pah[2], pah[3], bl[0], bl[1]);
                mma_bf16(o[dp * 2 + 1], pah[0], pah[1], pah[2], pah[3], bl[2], bl[3]);
            }
        }
    }

    // ---- epilogue: normalize, split, store in [B,S,H*D] ----
    float inv0 = 1.f / lrow0;
    float inv1 = 1.f / lrow1;
    int r0 = q0 + warp * 16 + gid;
    int r1 = r0 + 8;
    #pragma unroll
    for (int nt = 0; nt < 16; nt++) {
        int c = h * HDIM + nt * 8 + tig * 2;
        size_t i0 = (size_t)(b * SEQ + r0) * HIDDEN + c;
        size_t i1 = (size_t)(b * SEQ + r1) * HIDDEN + c;
        split_store2(Oh, Ol, i0, o[nt][0] * inv0, o[nt][1] * inv0);
        split_store2(Oh, Ol, i1, o[nt][2] * inv1, o[nt][3] * inv1);
    }
}

// =================================================================
// Broadcast single-KV-head K,V to [B,H,S,D] cache outputs
// =================================================================
__global__ __launch_bounds__(256) void bcast_kv_kernel(
    const float* __restrict__ K, const float* __restrict__ V,
    float* __restrict__ kout, float* __restrict__ vout)
{
    size_t idx = (size_t)blockIdx.x * blockDim.x + threadIdx.x;
    size_t total = KV_ELEMS;
    if (idx >= total) return;
    int b = (int)(idx / ((size_t)SEQ * HDIM));
    size_t rem = idx - (size_t)b * SEQ * HDIM;
    float kv = K[idx];
    float vv = V[idx];
    #pragma unroll
    for (int hh = 0; hh < NHEADS; hh++) {
        size_t oidx = ((size_t)b * NHEADS + hh) * SEQ * HDIM + rem;
        kout[oidx] = kv;
        vout[oidx] = vv;
    }
}

// =================================================================
extern "C" void kernel_launch(void* const* d_in, const int* in_sizes, int n_in,
                              void* d_out, int out_size) {
    const float* hs   = (const float*)d_in[0];
    const float* mask = (const float*)d_in[1];
    const float* Wq   = (const float*)d_in[2];
    const float* Wk   = (const float*)d_in[3];
    const float* Wv   = (const float*)d_in[4];
    const float* Wo   = (const float*)d_in[5];
    float* out = (float*)d_out;

    bf16 *hsH, *hsL, *WqH, *WqL, *WkH, *WkL, *WvH, *WvL, *WoH, *WoL;
    bf16 *QH, *QL, *KH, *KL, *VH, *VL, *AH, *AL;
    float *Kf, *Vf;
    cudaGetSymbolAddress((void**)&hsH, g_hsH); cudaGetSymbolAddress((void**)&hsL, g_hsL);
    cudaGetSymbolAddress((void**)&WqH, g_WqH); cudaGetSymbolAddress((void**)&WqL, g_WqL);
    cudaGetSymbolAddress((void**)&WkH, g_WkH); cudaGetSymbolAddress((void**)&WkL, g_WkL);
    cudaGetSymbolAddress((void**)&WvH, g_WvH); cudaGetSymbolAddress((void**)&WvL, g_WvL);
    cudaGetSymbolAddress((void**)&WoH, g_WoH); cudaGetSymbolAddress((void**)&WoL, g_WoL);
    cudaGetSymbolAddress((void**)&QH, g_QH);   cudaGetSymbolAddress((void**)&QL, g_QL);
    cudaGetSymbolAddress((void**)&KH, g_KH);   cudaGetSymbolAddress((void**)&KL, g_KL);
    cudaGetSymbolAddress((void**)&VH, g_VH);   cudaGetSymbolAddress((void**)&VL, g_VL);
    cudaGetSymbolAddress((void**)&AH, g_AH);   cudaGetSymbolAddress((void**)&AL, g_AL);
    cudaGetSymbolAddress((void**)&Kf, g_Kf);   cudaGetSymbolAddress((void**)&Vf, g_Vf);

    cudaFuncSetAttribute(gemm3_kernel, cudaFuncAttributeMaxDynamicSharedMemorySize, GEMM_SMEM);
    cudaFuncSetAttribute(attn3_kernel, cudaFuncAttributeMaxDynamicSharedMemorySize, ATTN_SMEM);

    // fused split of all inputs into bf16 hi/lo
    split_all_kernel<<<(unsigned)((N4_ALL + 255) / 256), 256>>>(
        hs, hsH, hsL, Wq, WqH, WqL, Wk, WkH, WkL, Wv, WvH, WvL, Wo, WoH, WoL);

    // Q projection: hi/lo out only
    gemm3_kernel<<<dim3(HIDDEN / GBN, MTOT / GBM, 1), 256, GEMM_SMEM>>>(
        hsH, hsL, WqH, WqL, nullptr, QH, QL,
        nullptr, nullptr, nullptr, nullptr, nullptr, MTOT, HIDDEN, HIDDEN);

    // K and V projections fused via blockIdx.z (fp32 for cache + hi/lo for attn)
    gemm3_kernel<<<dim3(HDIM / GBN, MTOT / GBM, 2), 256, GEMM_SMEM>>>(
        hsH, hsL, WkH, WkL, Kf, KH, KL,
        WvH, WvL, Vf, VH, VL, MTOT, HDIM, HIDDEN);

    // KV cache outputs
    if ((size_t)out_size >= OUT_ELEMS + 2 * CACHE_ELEMS) {
        bcast_kv_kernel<<<(unsigned)((KV_ELEMS + 255) / 256), 256>>>(
            Kf, Vf, out + OUT_ELEMS, out + OUT_ELEMS + CACHE_ELEMS);
    }

    // flash attention -> A (hi/lo)
    attn3_kernel<<<dim3(SEQ / ABM, NHEADS, BATCH), 128, ATTN_SMEM>>>(
        QH, QL, KH, KL, VH, VL, mask, AH, AL);

    // output projection -> fp32 out
    gemm3_kernel<<<dim3(HIDDEN / GBN, MTOT / GBM, 1), 256, GEMM_SMEM>>>(
        AH, AL, WoH, WoL, out, nullptr, nullptr,
        nullptr, nullptr, nullptr, nullptr, nullptr, MTOT, HIDDEN, HIDDEN);
}

// round 13
// speedup vs baseline: 1.6249x; 1.0748x over previous
#include <cuda_runtime.h>
#include <cuda_bf16.h>
#include <math.h>
#include <stdint.h>

using bf16 = __nv_bfloat16;

#define HIDDEN   2048
#define NHEADS   16
#define HDIM     128
#define BATCH    2
#define SEQ      2048
#define MTOT     (BATCH * SEQ)                         // 4096
#define OUT_ELEMS   ((size_t)MTOT * HIDDEN)            // 8388608
#define KV_ELEMS    ((size_t)MTOT * HDIM)              // 524288
#define CACHE_ELEMS ((size_t)BATCH * NHEADS * SEQ * HDIM)

// ---------------- scratch (__device__ globals; no allocation) ----------------
__device__ bf16 g_hsH[OUT_ELEMS], g_hsL[OUT_ELEMS];
__device__ bf16 g_WqH[(size_t)HIDDEN * HIDDEN], g_WqL[(size_t)HIDDEN * HIDDEN];
__device__ bf16 g_WkH[(size_t)HDIM * HIDDEN],  g_WkL[(size_t)HDIM * HIDDEN];
__device__ bf16 g_WvH[(size_t)HDIM * HIDDEN],  g_WvL[(size_t)HDIM * HIDDEN];
__device__ bf16 g_WoH[(size_t)HIDDEN * HIDDEN], g_WoL[(size_t)HIDDEN * HIDDEN];
__device__ bf16 g_QH[OUT_ELEMS], g_QL[OUT_ELEMS];
__device__ bf16 g_KH[KV_ELEMS], g_KL[KV_ELEMS];
__device__ bf16 g_VH[KV_ELEMS], g_VL[KV_ELEMS];
__device__ bf16 g_AH[OUT_ELEMS], g_AL[OUT_ELEMS];

// ---------------- low-level helpers ----------------
__device__ __forceinline__ uint32_t smem_u32(const void* p) {
    return (uint32_t)__cvta_generic_to_shared(p);
}
__device__ __forceinline__ void cp16(void* dst, const void* src) {
    asm volatile("cp.async.cg.shared.global [%0], [%1], 16;\n"
                 :: "r"(smem_u32(dst)), "l"(src));
}
__device__ __forceinline__ void cp_commit() { asm volatile("cp.async.commit_group;\n"); }
template<int N> __device__ __forceinline__ void cp_wait() {
    asm volatile("cp.async.wait_group %0;\n" :: "n"(N));
}
__device__ __forceinline__ void ldsm4(uint32_t& r0, uint32_t& r1, uint32_t& r2, uint32_t& r3,
                                      uint32_t addr) {
    asm volatile("ldmatrix.sync.aligned.m8n8.x4.shared.b16 {%0,%1,%2,%3},[%4];\n"
                 : "=r"(r0), "=r"(r1), "=r"(r2), "=r"(r3) : "r"(addr));
}
__device__ __forceinline__ void ldsm4t(uint32_t& r0, uint32_t& r1, uint32_t& r2, uint32_t& r3,
                                       uint32_t addr) {
    asm volatile("ldmatrix.sync.aligned.m8n8.x4.trans.shared.b16 {%0,%1,%2,%3},[%4];\n"
                 : "=r"(r0), "=r"(r1), "=r"(r2), "=r"(r3) : "r"(addr));
}
__device__ __forceinline__ void mma_bf16(float* c, uint32_t a0, uint32_t a1, uint32_t a2,
                                         uint32_t a3, uint32_t b0, uint32_t b1) {
    asm volatile(
        "mma.sync.aligned.m16n8k16.row.col.f32.bf16.bf16.f32 "
        "{%0,%1,%2,%3},{%4,%5,%6,%7},{%8,%9},{%0,%1,%2,%3};\n"
        : "+f"(c[0]), "+f"(c[1]), "+f"(c[2]), "+f"(c[3])
        : "r"(a0), "r"(a1), "r"(a2), "r"(a3), "r"(b0), "r"(b1));
}
__device__ __forceinline__ uint32_t bpack(float a, float b) {
    __nv_bfloat162 t;
    t.x = __float2bfloat16(a);
    t.y = __float2bfloat16(b);
    return *reinterpret_cast<uint32_t*>(&t);
}
__device__ __forceinline__ void split_store2(bf16* H, bf16* L, size_t idx, float x, float y) {
    float hx = __bfloat162float(__float2bfloat16(x));
    float hy = __bfloat162float(__float2bfloat16(y));
    uint32_t hh = bpack(hx, hy);
    uint32_t ll = bpack(x - hx, y - hy);
    *reinterpret_cast<uint32_t*>(H + idx) = hh;
    *reinterpret_cast<uint32_t*>(L + idx) = ll;
}

// ---------------- fused split: fp32 -> bf16 hi/lo, 5 tensors, one launch ----------------
__device__ __forceinline__ void split_one(const float* __restrict__ x,
                                          bf16* __restrict__ h, bf16* __restrict__ l,
                                          size_t i4) {
    size_t i = i4 * 4;
    float4 v = *reinterpret_cast<const float4*>(x + i);
    float h0 = __bfloat162float(__float2bfloat16(v.x));
    float h1 = __bfloat162float(__float2bfloat16(v.y));
    float h2 = __bfloat162float(__float2bfloat16(v.z));
    float h3 = __bfloat162float(__float2bfloat16(v.w));
    uint2 hp = make_uint2(bpack(h0, h1), bpack(h2, h3));
    uint2 lp = make_uint2(bpack(v.x - h0, v.y - h1), bpack(v.z - h2, v.w - h3));
    *reinterpret_cast<uint2*>(h + i) = hp;
    *reinterpret_cast<uint2*>(l + i) = lp;
}

#define N4_HS  ((size_t)OUT_ELEMS / 4)                 // 2097152
#define N4_WQ  ((size_t)HIDDEN * HIDDEN / 4)           // 1048576
#define N4_WK  ((size_t)HDIM * HIDDEN / 4)             // 65536
#define N4_ALL (N4_HS + 2 * N4_WQ + 2 * N4_WK)         // 4325376

__global__ __launch_bounds__(256) void split_all_kernel(
    const float* __restrict__ hs, bf16* __restrict__ hsH, bf16* __restrict__ hsL,
    const float* __restrict__ Wq, bf16* __restrict__ WqH, bf16* __restrict__ WqL,
    const float* __restrict__ Wk, bf16* __restrict__ WkH, bf16* __restrict__ WkL,
    const float* __restrict__ Wv, bf16* __restrict__ WvH, bf16* __restrict__ WvL,
    const float* __restrict__ Wo, bf16* __restrict__ WoH, bf16* __restrict__ WoL)
{
    size_t i = (size_t)blockIdx.x * blockDim.x + threadIdx.x;
    if (i >= N4_ALL) return;
    if (i < N4_HS) { split_one(hs, hsH, hsL, i); return; }
    i -= N4_HS;
    if (i < N4_WQ) { split_one(Wq, WqH, WqL, i); return; }
    i -= N4_WQ;
    if (i < N4_WK) { split_one(Wk, WkH, WkL, i); return; }
    i -= N4_WK;
    if (i < N4_WK) { split_one(Wv, WvH, WvL, i); return; }
    i -= N4_WK;
    split_one(Wo, WoH, WoL, i);
}

// =================================================================
// Shared GEMM tile constants (128x128x32, 256 threads, warp tile 64x32)
// =================================================================
#define GBM 128
#define GBN 128
#define GBK 32
#define GSTR 40
#define GTILE (GBM * GSTR)
#define GEMM_SMEM (2 * 4 * GTILE * 2)

// ---------------- bf16x3 GEMM mainloop (shared by both gemm kernels) ----------
struct GemmCore {
    float acc[4][4][4];
    __device__ __forceinline__ void run(bf16* smg, const bf16* Ah, const bf16* Al,
                                        const bf16* Wh, const bf16* Wl,
                                        int bm, int bn, int K, int tid) {
        const int lane = tid & 31;
        const int warp = tid >> 5;
        const int wm = (warp >> 2) * 64;
        const int wn = (warp & 3) * 32;
        #pragma unroll
        for (int a = 0; a < 4; a++)
            #pragma unroll
            for (int b = 0; b < 4; b++)
                #pragma unroll
                for (int c = 0; c < 4; c++) acc[a][b][c] = 0.f;

        const int T = K / GBK;
        auto load_stage = [&](int t, int buf) {
            bf16* base = smg + buf * (4 * GTILE);
            const int k0 = t * GBK;
            #pragma unroll
            for (int p = 0; p < 2; p++) {
                int q = tid + p * 256;
                int r = q >> 2;
                int c = (q & 3) * 8;
                size_t aoff = (size_t)(bm + r) * K + k0 + c;
                size_t woff = (size_t)(bn + r) * K + k0 + c;
                int soff = r * GSTR + c;
                cp16(base + soff,             Ah + aoff);
                cp16(base + GTILE + soff,     Al + aoff);
                cp16(base + 2 * GTILE + soff, Wh + woff);
                cp16(base + 3 * GTILE + soff, Wl + woff);
            }
        };

        load_stage(0, 0);
        cp_commit();

        const int arow = (lane & 15);
        const int acol = (lane >> 4) * 8;
        const int bnrow = (lane & 7) + ((lane & 16) ? 8 : 0);
        const int bkofs = (lane & 8) ? 8 : 0;

        for (int t = 0; t < T; t++) {
            if (t + 1 < T) { load_stage(t + 1, (t + 1) & 1); cp_commit(); cp_wait<1>(); }
            else           { cp_wait<0>(); }
            __syncthreads();

            bf16* base = smg + (t & 1) * (4 * GTILE);
            bf16* sAh = base;
            bf16* sAl = base + GTILE;
            bf16* sWh = base + 2 * GTILE;
            bf16* sWl = base + 3 * GTILE;

            #pragma unroll
            for (int kt = 0; kt < 2; kt++) {
                uint32_t ah[4][4], al[4][4];
                #pragma unroll
                for (int mt = 0; mt < 4; mt++) {
                    ldsm4(ah[mt][0], ah[mt][1], ah[mt][2], ah[mt][3],
                          smem_u32(sAh + (wm + mt * 16 + arow) * GSTR + kt * 16 + acol));
                    ldsm4(al[mt][0], al[mt][1], al[mt][2], al[mt][3],
                          smem_u32(sAl + (wm + mt * 16 + arow) * GSTR + kt * 16 + acol));
                }
                #pragma unroll
                for (int np = 0; np < 2; np++) {
                    uint32_t bh[4];
                    ldsm4(bh[0], bh[1], bh[2], bh[3],
                          smem_u32(sWh + (wn + np * 16 + bnrow) * GSTR + kt * 16 + bkofs));
                    #pragma unroll
                    for (int mt = 0; mt < 4; mt++) {
                        mma_bf16(acc[mt][np * 2],     ah[mt][0], ah[mt][1], ah[mt][2], ah[mt][3], bh[0], bh[1]);
                        mma_bf16(acc[mt][np * 2 + 1], ah[mt][0], ah[mt][1], ah[mt][2], ah[mt][3], bh[2], bh[3]);
                        mma_bf16(acc[mt][np * 2],     al[mt][0], al[mt][1], al[mt][2], al[mt][3], bh[0], bh[1]);
                        mma_bf16(acc[mt][np * 2 + 1], al[mt][0], al[mt][1], al[mt][2], al[mt][3], bh[2], bh[3]);
                    }
                    uint32_t bl[4];
                    ldsm4(bl[0], bl[1], bl[2], bl[3],
                          smem_u32(sWl + (wn + np * 16 + bnrow) * GSTR + kt * 16 + bkofs));
                    #pragma unroll
                    for (int mt = 0; mt < 4; mt++) {
                        mma_bf16(acc[mt][np * 2],     ah[mt][0], ah[mt][1], ah[mt][2], ah[mt][3], bl[0], bl[1]);
                        mma_bf16(acc[mt][np * 2 + 1], ah[mt][0], ah[mt][1], ah[mt][2], ah[mt][3], bl[2], bl[3]);
                    }
                }
            }
            __syncthreads();
        }
    }
};

// =================================================================
// Packed projection kernel: one launch computes Q, K, V projections.
// Grid: 576 CTAs 1D.  ids 0..63 -> K/V tiles (N=128), ids 64..575 -> Q tiles.
// KV CTAs also write the fp32 broadcast KV cache (replaces bcast kernel).
// =================================================================
__global__ __launch_bounds__(256, 2) void proj_all_kernel(
    const bf16* __restrict__ Ah, const bf16* __restrict__ Al,
    const bf16* __restrict__ WqH, const bf16* __restrict__ WqL,
    bf16* __restrict__ QH, bf16* __restrict__ QL,
    const bf16* __restrict__ WkH, const bf16* __restrict__ WkL,
    bf16* __restrict__ KH, bf16* __restrict__ KL,
    const bf16* __restrict__ WvH, const bf16* __restrict__ WvL,
    bf16* __restrict__ VH, bf16* __restrict__ VL,
    float* __restrict__ kout, float* __restrict__ vout)   // may be null
{
    extern __shared__ bf16 smg[];
    const int tid = threadIdx.x;
    const int id = blockIdx.x;

    const bf16 *Wh, *Wl;
    bf16 *Ch, *Cl;
    float* cache = nullptr;
    int bm, bn, N;
    if (id < 64) {
        int sel = id >> 5;          // 0=K, 1=V
        bm = (id & 31) * GBM; bn = 0; N = HDIM;
        if (sel == 0) { Wh = WkH; Wl = WkL; Ch = KH; Cl = KL; cache = kout; }
        else          { Wh = WvH; Wl = WvL; Ch = VH; Cl = VL; cache = vout; }
    } else {
        int j = id - 64;
        bm = (j >> 4) * GBM; bn = (j & 15) * GBN; N = HIDDEN;
        Wh = WqH; Wl = WqL; Ch = QH; Cl = QL;
    }

    GemmCore core;
    core.run(smg, Ah, Al, Wh, Wl, bm, bn, HIDDEN, tid);

    const int lane = tid & 31;
    const int warp = tid >> 5;
    const int wm = (warp >> 2) * 64;
    const int wn = (warp & 3) * 32;
    const int gid = lane >> 2;
    const int tig = lane & 3;

    #pragma unroll
    for (int mt = 0; mt < 4; mt++) {
        int r0 = bm + wm + mt * 16 + gid;
        int r1 = r0 + 8;
        #pragma unroll
        for (int nt = 0; nt < 4; nt++) {
            int c = bn + wn + nt * 8 + tig * 2;
            float* a = core.acc[mt][nt];
            split_store2(Ch, Cl, (size_t)r0 * N + c, a[0], a[1]);
            split_store2(Ch, Cl, (size_t)r1 * N + c, a[2], a[3]);
            if (cache) {
                // broadcast fp32 to all 16 heads: [b][h][s][d]
                int b0r = r0 >> 11, s0 = r0 & 2047;
                int b1r = r1 >> 11, s1 = r1 & 2047;
                float2 v0 = make_float2(a[0], a[1]);
                float2 v1 = make_float2(a[2], a[3]);
                size_t base0 = ((size_t)b0r * NHEADS * SEQ + s0) * HDIM + c;
                size_t base1 = ((size_t)b1r * NHEADS * SEQ + s1) * HDIM + c;
                #pragma unroll
                for (int hh = 0; hh < NHEADS; hh++) {
                    *reinterpret_cast<float2*>(&cache[base0 + (size_t)hh * SEQ * HDIM]) = v0;
                    *reinterpret_cast<float2*>(&cache[base1 + (size_t)hh * SEQ * HDIM]) = v1;
                }
            }
        }
    }
}

// =================================================================
// O-projection GEMM (fp32 out only)
// =================================================================
__global__ __launch_bounds__(256, 2) void gemmO_kernel(
    const bf16* __restrict__ Ah, const bf16* __restrict__ Al,
    const bf16* __restrict__ Wh, const bf16* __restrict__ Wl,
    float* __restrict__ Cf, int M, int N, int K)
{
    extern __shared__ bf16 smg[];
    const int tid = threadIdx.x;
    const int bm = blockIdx.y * GBM;
    const int bn = blockIdx.x * GBN;

    GemmCore core;
    core.run(smg, Ah, Al, Wh, Wl, bm, bn, K, tid);

    const int lane = tid & 31;
    const int warp = tid >> 5;
    const int wm = (warp >> 2) * 64;
    const int wn = (warp & 3) * 32;
    const int gid = lane >> 2;
    const int tig = lane & 3;
    #pragma unroll
    for (int mt = 0; mt < 4; mt++) {
        int r0 = bm + wm + mt * 16 + gid;
        int r1 = r0 + 8;
        #pragma unroll
        for (int nt = 0; nt < 4; nt++) {
            int c = bn + wn + nt * 8 + tig * 2;
            float* a = core.acc[mt][nt];
            *reinterpret_cast<float2*>(&Cf[(size_t)r0 * N + c]) = make_float2(a[0], a[1]);
            *reinterpret_cast<float2*>(&Cf[(size_t)r1 * N + c]) = make_float2(a[2], a[3]);
        }
    }
}

// =================================================================
// Flash attention with bf16x3 mma.  (R6 winning configuration)
// CTA: 64 q rows, 128 threads (4 warps; warp owns 16 q rows, full d=128).
// =================================================================
#define ABM 64
#define ABN 64
#define DSTR 136
#define ATILE (ABM * DSTR)                       // b16 per array
#define ATTN_SMEM (6 * ATILE * 2 + 256)          // bytes

__global__ __launch_bounds__(128, 2) void attn3_kernel(
    const bf16* __restrict__ Qh, const bf16* __restrict__ Ql,
    const bf16* __restrict__ Kh, const bf16* __restrict__ Kl,
    const bf16* __restrict__ Vh, const bf16* __restrict__ Vl,
    const float* __restrict__ mask,
    bf16* __restrict__ Oh, bf16* __restrict__ Ol)
{
    extern __shared__ bf16 sma[];
    bf16* sQh = sma;
    bf16* sQl = sma + ATILE;
    bf16* sKh = sma + 2 * ATILE;
    bf16* sKl = sma + 3 * ATILE;
    bf16* sVh = sma + 4 * ATILE;
    bf16* sVl = sma + 5 * ATILE;
    float* sbias = reinterpret_cast<float*>(sma + 6 * ATILE);

    const int tid = threadIdx.x;
    const int lane = tid & 31;
    const int warp = tid >> 5;
    const int gid = lane >> 2;
    const int tig = lane & 3;
    const int b = blockIdx.z;
    const int h = blockIdx.y;
    const int q0 = blockIdx.x * ABM;
    const float scale = 0.08838834764831845f;   // 1/sqrt(128)

    // Q tile: 64 rows x 128 b16 (hi+lo)
    #pragma unroll
    for (int p = 0; p < 8; p++) {
        int idx = tid + p * 128;
        int r = idx >> 4;
        int c = (idx & 15) * 8;
        size_t g = ((size_t)(b * SEQ + q0 + r)) * HIDDEN + h * HDIM + c;
        cp16(sQh + r * DSTR + c, Qh + g);
        cp16(sQl + r * DSTR + c, Ql + g);
    }
    cp_commit();

    float o[16][4];
    #pragma unroll
    for (int i = 0; i < 16; i++)
        #pragma unroll
        for (int j = 0; j < 4; j++) o[i][j] = 0.f;
    float mrow0 = -1e30f, mrow1 = -1e30f;
    float lrow0 = 0.f, lrow1 = 0.f;

    const int arow = warp * 16 + (lane & 15);
    const int acol = (lane >> 4) * 8;
    const int bnrow = (lane & 7) + ((lane & 16) ? 8 : 0);
    const int bkofs = (lane & 8) ? 8 : 0;
    const int vrow = lane & 15;
    const int vd = (lane >> 4) * 8;

    for (int k0 = 0; k0 < SEQ; k0 += ABN) {
        __syncthreads();
        #pragma unroll
        for (int p = 0; p < 8; p++) {
            int idx = tid + p * 128;
            int r = idx >> 4;
            int c = (idx & 15) * 8;
            size_t g = ((size_t)(b * SEQ + k0 + r)) * HDIM + c;
            int s = r * DSTR + c;
            cp16(sKh + s, Kh + g);
            cp16(sKl + s, Kl + g);
            cp16(sVh + s, Vh + g);
            cp16(sVl + s, Vl + g);
        }
        if (tid < ABN) sbias[tid] = (1.0f - mask[(size_t)b * SEQ + k0 + tid]) * -1e30f;
        cp_commit();
        cp_wait<0>();
        __syncthreads();

        // ---- S = Q K^T (bf16x3) ----
        float s[8][4];
        #pragma unroll
        for (int i = 0; i < 8; i++)
            #pragma unroll
            for (int j = 0; j < 4; j++) s[i][j] = 0.f;

        #pragma unroll
        for (int kt = 0; kt < 8; kt++) {
            uint32_t ah[4], al2[4];
            ldsm4(ah[0], ah[1], ah[2], ah[3],
                  smem_u32(sQh + arow * DSTR + kt * 16 + acol));
            ldsm4(al2[0], al2[1], al2[2], al2[3],
                  smem_u32(sQl + arow * DSTR + kt * 16 + acol));
            #pragma unroll
            for (int np = 0; np < 4; np++) {
                uint32_t bh[4];
                ldsm4(bh[0], bh[1], bh[2], bh[3],
                      smem_u32(sKh + (np * 16 + bnrow) * DSTR + kt * 16 + bkofs));
                mma_bf16(s[np * 2],     ah[0], ah[1], ah[2], ah[3], bh[0], bh[1]);
                mma_bf16(s[np * 2 + 1], ah[0], ah[1], ah[2], ah[3], bh[2], bh[3]);
                mma_bf16(s[np * 2],     al2[0], al2[1], al2[2], al2[3], bh[0], bh[1]);
                mma_bf16(s[np * 2 + 1], al2[0], al2[1], al2[2], al2[3], bh[2], bh[3]);
                uint32_t bl[4];
                ldsm4(bl[0], bl[1], bl[2], bl[3],
                      smem_u32(sKl + (np * 16 + bnrow) * DSTR + kt * 16 + bkofs));
                mma_bf16(s[np * 2],     ah[0], ah[1], ah[2], ah[3], bl[0], bl[1]);
                mma_bf16(s[np * 2 + 1], ah[0], ah[1], ah[2], ah[3], bl[2], bl[3]);
            }
        }

        // ---- online softmax (rows gid and gid+8 of this warp's 16) ----
        float mn0 = mrow0, mn1 = mrow1;
        #pragma unroll
        for (int nt = 0; nt < 8; nt++) {
            int c = nt * 8 + tig * 2;
            float b0 = sbias[c], b1 = sbias[c + 1];
            s[nt][0] = s[nt][0] * scale + b0;
            s[nt][1] = s[nt][1] * scale + b1;
            s[nt][2] = s[nt][2] * scale + b0;
            s[nt][3] = s[nt][3] * scale + b1;
            mn0 = fmaxf(mn0, fmaxf(s[nt][0], s[nt][1]));
            mn1 = fmaxf(mn1, fmaxf(s[nt][2], s[nt][3]));
        }
        mn0 = fmaxf(mn0, __shfl_xor_sync(0xffffffffu, mn0, 1));
        mn0 = fmaxf(mn0, __shfl_xor_sync(0xffffffffu, mn0, 2));
        mn1 = fmaxf(mn1, __shfl_xor_sync(0xffffffffu, mn1, 1));
        mn1 = fmaxf(mn1, __shfl_xor_sync(0xffffffffu, mn1, 2));
        float alpha0 = __expf(mrow0 - mn0);
        float alpha1 = __expf(mrow1 - mn1);
        mrow0 = mn0; mrow1 = mn1;

        float rs0 = 0.f, rs1 = 0.f;
        #pragma unroll
        for (int nt = 0; nt < 8; nt++) {
            s[nt][0] = __expf(s[nt][0] - mn0);
            s[nt][1] = __expf(s[nt][1] - mn0);
            s[nt][2] = __expf(s[nt][2] - mn1);
            s[nt][3] = __expf(s[nt][3] - mn1);
            rs0 += s[nt][0] + s[nt][1];
            rs1 += s[nt][2] + s[nt][3];
        }
        rs0 += __shfl_xor_sync(0xffffffffu, rs0, 1);
        rs0 += __shfl_xor_sync(0xffffffffu, rs0, 2);
        rs1 += __shfl_xor_sync(0xffffffffu, rs1, 1);
        rs1 += __shfl_xor_sync(0xffffffffu, rs1, 2);
        lrow0 = lrow0 * alpha0 + rs0;
        lrow1 = lrow1 * alpha1 + rs1;
        #pragma unroll
        for (int nt = 0; nt < 16; nt++) {
            o[nt][0] *= alpha0; o[nt][1] *= alpha0;
            o[nt][2] *= alpha1; o[nt][3] *= alpha1;
        }

        // ---- O += P V (bf16x3, P split in regs) ----
        #pragma unroll
        for (int t2 = 0; t2 < 4; t2++) {
            float* p0 = s[2 * t2];
            float* p1 = s[2 * t2 + 1];
            float h00 = __bfloat162float(__float2bfloat16(p0[0]));
            float h01 = __bfloat162float(__float2bfloat16(p0[1]));
            float h02 = __bfloat162float(__float2bfloat16(p0[2]));
            float h03 = __bfloat162float(__float2bfloat16(p0[3]));
            float h10 = __bfloat162float(__float2bfloat16(p1[0]));
            float h11 = __bfloat162float(__float2bfloat16(p1[1]));
            float h12 = __bfloat162float(__float2bfloat16(p1[2]));
            float h13 = __bfloat162float(__float2bfloat16(p1[3]));
            uint32_t pah[4] = { bpack(h00, h01), bpack(h02, h03), bpack(h10, h11), bpack(h12, h13) };
            uint32_t pal[4] = { bpack(p0[0] - h00, p0[1] - h01), bpack(p0[2] - h02, p0[3] - h03),
                                bpack(p1[0] - h10, p1[1] - h11), bpack(p1[2] - h12, p1[3] - h13) };
            #pragma unroll
            for (int dp = 0; dp < 8; dp++) {
                uint32_t bh[4];
                ldsm4t(bh[0], bh[1], bh[2], bh[3],
                       smem_u32(sVh + (t2 * 16 + vrow) * DSTR + dp * 16 + vd));
                mma_bf16(o[dp * 2],     pah[0], pah[1], pah[2], pah[3], bh[0], bh[1]);
                mma_bf16(o[dp * 2 + 1], pah[0], pah[1], pah[2], pah[3], bh[2], bh[3]);
                mma_bf16(o[dp * 2],     pal[0], pal[1], pal[2], pal[3], bh[0], bh[1]);
                mma_bf16(o[dp * 2 + 1], pal[0], pal[1], pal[2], pal[3], bh[2], bh[3]);
                uint32_t bl[4];
                ldsm4t(bl[0], bl[1], bl[2], bl[3],
                       smem_u32(sVl + (t2 * 16 + vrow) * DSTR + dp * 16 + vd));
                mma_bf16(o[dp * 2],     pah[0], pah[1], pah[2], pah[3], bl[0], bl[1]);
                mma_bf16(o[dp * 2 + 1], pah[0], pah[1], pah[2], pah[3], bl[2], bl[3]);
            }
        }
    }

    // ---- epilogue: normalize, split, store in [B,S,H*D] ----
    float inv0 = 1.f / lrow0;
    float inv1 = 1.f / lrow1;
    int r0 = q0 + warp * 16 + gid;
    int r1 = r0 + 8;
    #pragma unroll
    for (int nt = 0; nt < 16; nt++) {
        int c = h * HDIM + nt * 8 + tig * 2;
        size_t i0 = (size_t)(b * SEQ + r0) * HIDDEN + c;
        size_t i1 = (size_t)(b * SEQ + r1) * HIDDEN + c;
        split_store2(Oh, Ol, i0, o[nt][0] * inv0, o[nt][1] * inv0);
        split_store2(Oh, Ol, i1, o[nt][2] * inv1, o[nt][3] * inv1);
    }
}

// =================================================================
extern "C" void kernel_launch(void* const* d_in, const int* in_sizes, int n_in,
                              void* d_out, int out_size) {
    const float* hs   = (const float*)d_in[0];
    const float* mask = (const float*)d_in[1];
    const float* Wq   = (const float*)d_in[2];
    const float* Wk   = (const float*)d_in[3];
    const float* Wv   = (const float*)d_in[4];
    const float* Wo   = (const float*)d_in[5];
    float* out = (float*)d_out;

    bf16 *hsH, *hsL, *WqH, *WqL, *WkH, *WkL, *WvH, *WvL, *WoH, *WoL;
    bf16 *QH, *QL, *KH, *KL, *VH, *VL, *AH, *AL;
    cudaGetSymbolAddress((void**)&hsH, g_hsH); cudaGetSymbolAddress((void**)&hsL, g_hsL);
    cudaGetSymbolAddress((void**)&WqH, g_WqH); cudaGetSymbolAddress((void**)&WqL, g_WqL);
    cudaGetSymbolAddress((void**)&WkH, g_WkH); cudaGetSymbolAddress((void**)&WkL, g_WkL);
    cudaGetSymbolAddress((void**)&WvH, g_WvH); cudaGetSymbolAddress((void**)&WvL, g_WvL);
    cudaGetSymbolAddress((void**)&WoH, g_WoH); cudaGetSymbolAddress((void**)&WoL, g_WoL);
    cudaGetSymbolAddress((void**)&QH, g_QH);   cudaGetSymbolAddress((void**)&QL, g_QL);
    cudaGetSymbolAddress((void**)&KH, g_KH);   cudaGetSymbolAddress((void**)&KL, g_KL);
    cudaGetSymbolAddress((void**)&VH, g_VH);   cudaGetSymbolAddress((void**)&VL, g_VL);
    cudaGetSymbolAddress((void**)&AH, g_AH);   cudaGetSymbolAddress((void**)&AL, g_AL);

    cudaFuncSetAttribute(proj_all_kernel, cudaFuncAttributeMaxDynamicSharedMemorySize, GEMM_SMEM);
    cudaFuncSetAttribute(gemmO_kernel, cudaFuncAttributeMaxDynamicSharedMemorySize, GEMM_SMEM);
    cudaFuncSetAttribute(attn3_kernel, cudaFuncAttributeMaxDynamicSharedMemorySize, ATTN_SMEM);

    // fused split of all inputs into bf16 hi/lo
    split_all_kernel<<<(unsigned)((N4_ALL + 255) / 256), 256>>>(
        hs, hsH, hsL, Wq, WqH, WqL, Wk, WkH, WkL, Wv, WvH, WvL, Wo, WoH, WoL);

    // packed Q+K+V projections (KV CTAs also write broadcast fp32 cache)
    float* kout = nullptr;
    float* vout = nullptr;
    if ((size_t)out_size >= OUT_ELEMS + 2 * CACHE_ELEMS) {
        kout = out + OUT_ELEMS;
        vout = out + OUT_ELEMS + CACHE_ELEMS;
    }
    proj_all_kernel<<<576, 256, GEMM_SMEM>>>(
        hsH, hsL, WqH, WqL, QH, QL, WkH, WkL, KH, KL, WvH, WvL, VH, VL, kout, vout);

    // flash attention -> A (hi/lo)
    attn3_kernel<<<dim3(SEQ / ABM, NHEADS, BATCH), 128, ATTN_SMEM>>>(
        QH, QL, KH, KL, VH, VL, mask, AH, AL);

    // output projection -> fp32 out
    gemmO_kernel<<<dim3(HIDDEN / GBN, MTOT / GBM), 256, GEMM_SMEM>>>(
        AH, AL, WoH, WoL, out, MTOT, HIDDEN, HIDDEN);
}

// round 17
// speedup vs baseline: 1.6251x; 1.0001x over previous
#include <cuda_runtime.h>
#include <cuda_bf16.h>
#include <math.h>
#include <stdint.h>

using bf16 = __nv_bfloat16;

#define HIDDEN   2048
#define NHEADS   16
#define HDIM     128
#define BATCH    2
#define SEQ      2048
#define MTOT     (BATCH * SEQ)                         // 4096
#define OUT_ELEMS   ((size_t)MTOT * HIDDEN)            // 8388608
#define KV_ELEMS    ((size_t)MTOT * HDIM)              // 524288
#define CACHE_ELEMS ((size_t)BATCH * NHEADS * SEQ * HDIM)

// ---------------- scratch (__device__ globals; no allocation) ----------------
__device__ bf16 g_hsH[OUT_ELEMS], g_hsL[OUT_ELEMS];
__device__ bf16 g_WqH[(size_t)HIDDEN * HIDDEN], g_WqL[(size_t)HIDDEN * HIDDEN];
__device__ bf16 g_WkH[(size_t)HDIM * HIDDEN],  g_WkL[(size_t)HDIM * HIDDEN];
__device__ bf16 g_WvH[(size_t)HDIM * HIDDEN],  g_WvL[(size_t)HDIM * HIDDEN];
__device__ bf16 g_WoH[(size_t)HIDDEN * HIDDEN], g_WoL[(size_t)HIDDEN * HIDDEN];
__device__ bf16 g_QH[OUT_ELEMS], g_QL[OUT_ELEMS];
__device__ bf16 g_KH[KV_ELEMS], g_KL[KV_ELEMS];
__device__ bf16 g_VH[KV_ELEMS], g_VL[KV_ELEMS];
__device__ bf16 g_AH[OUT_ELEMS], g_AL[OUT_ELEMS];

// ---------------- low-level helpers ----------------
__device__ __forceinline__ uint32_t smem_u32(const void* p) {
    return (uint32_t)__cvta_generic_to_shared(p);
}
__device__ __forceinline__ void cp16(void* dst, const void* src) {
    asm volatile("cp.async.cg.shared.global [%0], [%1], 16;\n"
                 :: "r"(smem_u32(dst)), "l"(src));
}
__device__ __forceinline__ void cp_commit() { asm volatile("cp.async.commit_group;\n"); }
template<int N> __device__ __forceinline__ void cp_wait() {
    asm volatile("cp.async.wait_group %0;\n" :: "n"(N));
}
__device__ __forceinline__ void ldsm4(uint32_t& r0, uint32_t& r1, uint32_t& r2, uint32_t& r3,
                                      uint32_t addr) {
    asm volatile("ldmatrix.sync.aligned.m8n8.x4.shared.b16 {%0,%1,%2,%3},[%4];\n"
                 : "=r"(r0), "=r"(r1), "=r"(r2), "=r"(r3) : "r"(addr));
}
__device__ __forceinline__ void ldsm4t(uint32_t& r0, uint32_t& r1, uint32_t& r2, uint32_t& r3,
                                       uint32_t addr) {
    asm volatile("ldmatrix.sync.aligned.m8n8.x4.trans.shared.b16 {%0,%1,%2,%3},[%4];\n"
                 : "=r"(r0), "=r"(r1), "=r"(r2), "=r"(r3) : "r"(addr));
}
__device__ __forceinline__ void mma_bf16(float* c, uint32_t a0, uint32_t a1, uint32_t a2,
                                         uint32_t a3, uint32_t b0, uint32_t b1) {
    asm volatile(
        "mma.sync.aligned.m16n8k16.row.col.f32.bf16.bf16.f32 "
        "{%0,%1,%2,%3},{%4,%5,%6,%7},{%8,%9},{%0,%1,%2,%3};\n"
        : "+f"(c[0]), "+f"(c[1]), "+f"(c[2]), "+f"(c[3])
        : "r"(a0), "r"(a1), "r"(a2), "r"(a3), "r"(b0), "r"(b1));
}
__device__ __forceinline__ uint32_t bpack(float a, float b) {
    __nv_bfloat162 t;
    t.x = __float2bfloat16(a);
    t.y = __float2bfloat16(b);
    return *reinterpret_cast<uint32_t*>(&t);
}
__device__ __forceinline__ void split_store2(bf16* H, bf16* L, size_t idx, float x, float y) {
    float hx = __bfloat162float(__float2bfloat16(x));
    float hy = __bfloat162float(__float2bfloat16(y));
    uint32_t hh = bpack(hx, hy);
    uint32_t ll = bpack(x - hx, y - hy);
    *reinterpret_cast<uint32_t*>(H + idx) = hh;
    *reinterpret_cast<uint32_t*>(L + idx) = ll;
}

// ---------------- fused split: fp32 -> bf16 hi/lo, 5 tensors, one launch ----------------
__device__ __forceinline__ void split_one(const float* __restrict__ x,
                                          bf16* __restrict__ h, bf16* __restrict__ l,
                                          size_t i4) {
    size_t i = i4 * 4;
    float4 v = *reinterpret_cast<const float4*>(x + i);
    float h0 = __bfloat162float(__float2bfloat16(v.x));
    float h1 = __bfloat162float(__float2bfloat16(v.y));
    float h2 = __bfloat162float(__float2bfloat16(v.z));
    float h3 = __bfloat162float(__float2bfloat16(v.w));
    uint2 hp = make_uint2(bpack(h0, h1), bpack(h2, h3));
    uint2 lp = make_uint2(bpack(v.x - h0, v.y - h1), bpack(v.z - h2, v.w - h3));
    *reinterpret_cast<uint2*>(h + i) = hp;
    *reinterpret_cast<uint2*>(l + i) = lp;
}

#define N4_HS  ((size_t)OUT_ELEMS / 4)                 // 2097152
#define N4_WQ  ((size_t)HIDDEN * HIDDEN / 4)           // 1048576
#define N4_WK  ((size_t)HDIM * HIDDEN / 4)             // 65536
#define N4_ALL (N4_HS + 2 * N4_WQ + 2 * N4_WK)         // 4325376

__global__ __launch_bounds__(256) void split_all_kernel(
    const float* __restrict__ hs, bf16* __restrict__ hsH, bf16* __restrict__ hsL,
    const float* __restrict__ Wq, bf16* __restrict__ WqH, bf16* __restrict__ WqL,
    const float* __restrict__ Wk, bf16* __restrict__ WkH, bf16* __restrict__ WkL,
    const float* __restrict__ Wv, bf16* __restrict__ WvH, bf16* __restrict__ WvL,
    const float* __restrict__ Wo, bf16* __restrict__ WoH, bf16* __restrict__ WoL)
{
    size_t i = (size_t)blockIdx.x * blockDim.x + threadIdx.x;
    if (i >= N4_ALL) return;
    if (i < N4_HS) { split_one(hs, hsH, hsL, i); return; }
    i -= N4_HS;
    if (i < N4_WQ) { split_one(Wq, WqH, WqL, i); return; }
    i -= N4_WQ;
    if (i < N4_WK) { split_one(Wk, WkH, WkL, i); return; }
    i -= N4_WK;
    if (i < N4_WK) { split_one(Wv, WvH, WvL, i); return; }
    i -= N4_WK;
    split_one(Wo, WoH, WoL, i);
}

// =================================================================
// Shared GEMM tile constants (128x128x32, 256 threads, warp tile 64x32)
// =================================================================
#define GBM 128
#define GBN 128
#define GBK 32
#define GSTR 40
#define GTILE (GBM * GSTR)
#define GEMM_SMEM (2 * 4 * GTILE * 2)

// ---------------- bf16x3 GEMM mainloop (shared by both gemm kernels) ----------
struct GemmCore {
    float acc[4][4][4];
    __device__ __forceinline__ void run(bf16* smg, const bf16* Ah, const bf16* Al,
                                        const bf16* Wh, const bf16* Wl,
                                        int bm, int bn, int K, int tid) {
        const int lane = tid & 31;
        const int warp = tid >> 5;
        const int wm = (warp >> 2) * 64;
        const int wn = (warp & 3) * 32;
        #pragma unroll
        for (int a = 0; a < 4; a++)
            #pragma unroll
            for (int b = 0; b < 4; b++)
                #pragma unroll
                for (int c = 0; c < 4; c++) acc[a][b][c] = 0.f;

        const int T = K / GBK;
        auto load_stage = [&](int t, int buf) {
            bf16* base = smg + buf * (4 * GTILE);
            const int k0 = t * GBK;
            #pragma unroll
            for (int p = 0; p < 2; p++) {
                int q = tid + p * 256;
                int r = q >> 2;
                int c = (q & 3) * 8;
                size_t aoff = (size_t)(bm + r) * K + k0 + c;
                size_t woff = (size_t)(bn + r) * K + k0 + c;
                int soff = r * GSTR + c;
                cp16(base + soff,             Ah + aoff);
                cp16(base + GTILE + soff,     Al + aoff);
                cp16(base + 2 * GTILE + soff, Wh + woff);
                cp16(base + 3 * GTILE + soff, Wl + woff);
            }
        };

        load_stage(0, 0);
        cp_commit();

        const int arow = (lane & 15);
        const int acol = (lane >> 4) * 8;
        const int bnrow = (lane & 7) + ((lane & 16) ? 8 : 0);
        const int bkofs = (lane & 8) ? 8 : 0;

        for (int t = 0; t < T; t++) {
            if (t + 1 < T) { load_stage(t + 1, (t + 1) & 1); cp_commit(); cp_wait<1>(); }
            else           { cp_wait<0>(); }
            __syncthreads();

            bf16* base = smg + (t & 1) * (4 * GTILE);
            bf16* sAh = base;
            bf16* sAl = base + GTILE;
            bf16* sWh = base + 2 * GTILE;
            bf16* sWl = base + 3 * GTILE;

            #pragma unroll
            for (int kt = 0; kt < 2; kt++) {
                uint32_t ah[4][4], al[4][4];
                #pragma unroll
                for (int mt = 0; mt < 4; mt++) {
                    ldsm4(ah[mt][0], ah[mt][1], ah[mt][2], ah[mt][3],
                          smem_u32(sAh + (wm + mt * 16 + arow) * GSTR + kt * 16 + acol));
                    ldsm4(al[mt][0], al[mt][1], al[mt][2], al[mt][3],
                          smem_u32(sAl + (wm + mt * 16 + arow) * GSTR + kt * 16 + acol));
                }
                #pragma unroll
                for (int np = 0; np < 2; np++) {
                    uint32_t bh[4];
                    ldsm4(bh[0], bh[1], bh[2], bh[3],
                          smem_u32(sWh + (wn + np * 16 + bnrow) * GSTR + kt * 16 + bkofs));
                    #pragma unroll
                    for (int mt = 0; mt < 4; mt++) {
                        mma_bf16(acc[mt][np * 2],     ah[mt][0], ah[mt][1], ah[mt][2], ah[mt][3], bh[0], bh[1]);
                        mma_bf16(acc[mt][np * 2 + 1], ah[mt][0], ah[mt][1], ah[mt][2], ah[mt][3], bh[2], bh[3]);
                        mma_bf16(acc[mt][np * 2],     al[mt][0], al[mt][1], al[mt][2], al[mt][3], bh[0], bh[1]);
                        mma_bf16(acc[mt][np * 2 + 1], al[mt][0], al[mt][1], al[mt][2], al[mt][3], bh[2], bh[3]);
                    }
                    uint32_t bl[4];
                    ldsm4(bl[0], bl[1], bl[2], bl[3],
                          smem_u32(sWl + (wn + np * 16 + bnrow) * GSTR + kt * 16 + bkofs));
                    #pragma unroll
                    for (int mt = 0; mt < 4; mt++) {
                        mma_bf16(acc[mt][np * 2],     ah[mt][0], ah[mt][1], ah[mt][2], ah[mt][3], bl[0], bl[1]);
                        mma_bf16(acc[mt][np * 2 + 1], ah[mt][0], ah[mt][1], ah[mt][2], ah[mt][3], bl[2], bl[3]);
                    }
                }
            }
            __syncthreads();
        }
    }
};

// =================================================================
// Packed projection kernel: one launch computes Q, K, V projections.
// Grid: 576 CTAs 1D.  ids 0..63 -> K/V tiles (N=128), ids 64..575 -> Q tiles.
// KV CTAs also write the fp32 broadcast KV cache (replaces bcast kernel).
// =================================================================
__global__ __launch_bounds__(256, 2) void proj_all_kernel(
    const bf16* __restrict__ Ah, const bf16* __restrict__ Al,
    const bf16* __restrict__ WqH, const bf16* __restrict__ WqL,
    bf16* __restrict__ QH, bf16* __restrict__ QL,
    const bf16* __restrict__ WkH, const bf16* __restrict__ WkL,
    bf16* __restrict__ KH, bf16* __restrict__ KL,
    const bf16* __restrict__ WvH, const bf16* __restrict__ WvL,
    bf16* __restrict__ VH, bf16* __restrict__ VL,
    float* __restrict__ kout, float* __restrict__ vout)   // may be null
{
    extern __shared__ bf16 smg[];
    const int tid = threadIdx.x;
    const int id = blockIdx.x;

    const bf16 *Wh, *Wl;
    bf16 *Ch, *Cl;
    float* cache = nullptr;
    int bm, bn, N;
    if (id < 64) {
        int sel = id >> 5;          // 0=K, 1=V
        bm = (id & 31) * GBM; bn = 0; N = HDIM;
        if (sel == 0) { Wh = WkH; Wl = WkL; Ch = KH; Cl = KL; cache = kout; }
        else          { Wh = WvH; Wl = WvL; Ch = VH; Cl = VL; cache = vout; }
    } else {
        int j = id - 64;
        bm = (j >> 4) * GBM; bn = (j & 15) * GBN; N = HIDDEN;
        Wh = WqH; Wl = WqL; Ch = QH; Cl = QL;
    }

    GemmCore core;
    core.run(smg, Ah, Al, Wh, Wl, bm, bn, HIDDEN, tid);

    const int lane = tid & 31;
    const int warp = tid >> 5;
    const int wm = (warp >> 2) * 64;
    const int wn = (warp & 3) * 32;
    const int gid = lane >> 2;
    const int tig = lane & 3;

    #pragma unroll
    for (int mt = 0; mt < 4; mt++) {
        int r0 = bm + wm + mt * 16 + gid;
        int r1 = r0 + 8;
        #pragma unroll
        for (int nt = 0; nt < 4; nt++) {
            int c = bn + wn + nt * 8 + tig * 2;
            float* a = core.acc[mt][nt];
            split_store2(Ch, Cl, (size_t)r0 * N + c, a[0], a[1]);
            split_store2(Ch, Cl, (size_t)r1 * N + c, a[2], a[3]);
            if (cache) {
                // broadcast fp32 to all 16 heads: [b][h][s][d]
                int b0r = r0 >> 11, s0 = r0 & 2047;
                int b1r = r1 >> 11, s1 = r1 & 2047;
                float2 v0 = make_float2(a[0], a[1]);
                float2 v1 = make_float2(a[2], a[3]);
                size_t base0 = ((size_t)b0r * NHEADS * SEQ + s0) * HDIM + c;
                size_t base1 = ((size_t)b1r * NHEADS * SEQ + s1) * HDIM + c;
                #pragma unroll
                for (int hh = 0; hh < NHEADS; hh++) {
                    *reinterpret_cast<float2*>(&cache[base0 + (size_t)hh * SEQ * HDIM]) = v0;
                    *reinterpret_cast<float2*>(&cache[base1 + (size_t)hh * SEQ * HDIM]) = v1;
                }
            }
        }
    }
}

// =================================================================
// O-projection GEMM (fp32 out only)
// =================================================================
__global__ __launch_bounds__(256, 2) void gemmO_kernel(
    const bf16* __restrict__ Ah, const bf16* __restrict__ Al,
    const bf16* __restrict__ Wh, const bf16* __restrict__ Wl,
    float* __restrict__ Cf, int M, int N, int K)
{
    extern __shared__ bf16 smg[];
    const int tid = threadIdx.x;
    const int bm = blockIdx.y * GBM;
    const int bn = blockIdx.x * GBN;

    GemmCore core;
    core.run(smg, Ah, Al, Wh, Wl, bm, bn, K, tid);

    const int lane = tid & 31;
    const int warp = tid >> 5;
    const int wm = (warp >> 2) * 64;
    const int wn = (warp & 3) * 32;
    const int gid = lane >> 2;
    const int tig = lane & 3;
    #pragma unroll
    for (int mt = 0; mt < 4; mt++) {
        int r0 = bm + wm + mt * 16 + gid;
        int r1 = r0 + 8;
        #pragma unroll
        for (int nt = 0; nt < 4; nt++) {
            int c = bn + wn + nt * 8 + tig * 2;
            float* a = core.acc[mt][nt];
            *reinterpret_cast<float2*>(&Cf[(size_t)r0 * N + c]) = make_float2(a[0], a[1]);
            *reinterpret_cast<float2*>(&Cf[(size_t)r1 * N + c]) = make_float2(a[2], a[3]);
        }
    }
}

// =================================================================
// Flash attention with bf16x3 mma.  (R6 winning configuration)
// CTA: 64 q rows, 128 threads (4 warps; warp owns 16 q rows, full d=128).
// =================================================================
#define ABM 64
#define ABN 64
#define DSTR 136
#define ATILE (ABM * DSTR)                       // b16 per array
#define ATTN_SMEM (6 * ATILE * 2 + 256)          // bytes

__global__ __launch_bounds__(128, 2) void attn3_kernel(
    const bf16* __restrict__ Qh, const bf16* __restrict__ Ql,
    const bf16* __restrict__ Kh, const bf16* __restrict__ Kl,
    const bf16* __restrict__ Vh, const bf16* __restrict__ Vl,
    const float* __restrict__ mask,
    bf16* __restrict__ Oh, bf16* __restrict__ Ol)
{
    extern __shared__ bf16 sma[];
    bf16* sQh = sma;
    bf16* sQl = sma + ATILE;
    bf16* sKh = sma + 2 * ATILE;
    bf16* sKl = sma + 3 * ATILE;
    bf16* sVh = sma + 4 * ATILE;
    bf16* sVl = sma + 5 * ATILE;
    float* sbias = reinterpret_cast<float*>(sma + 6 * ATILE);

    const int tid = threadIdx.x;
    const int lane = tid & 31;
    const int warp = tid >> 5;
    const int gid = lane >> 2;
    const int tig = lane & 3;
    const int b = blockIdx.z;
    const int h = blockIdx.y;
    const int q0 = blockIdx.x * ABM;
    const float scale = 0.08838834764831845f;   // 1/sqrt(128)

    // Q tile: 64 rows x 128 b16 (hi+lo)
    #pragma unroll
    for (int p = 0; p < 8; p++) {
        int idx = tid + p * 128;
        int r = idx >> 4;
        int c = (idx & 15) * 8;
        size_t g = ((size_t)(b * SEQ + q0 + r)) * HIDDEN + h * HDIM + c;
        cp16(sQh + r * DSTR + c, Qh + g);
        cp16(sQl + r * DSTR + c, Ql + g);
    }
    cp_commit();

    float o[16][4];
    #pragma unroll
    for (int i = 0; i < 16; i++)
        #pragma unroll
        for (int j = 0; j < 4; j++) o[i][j] = 0.f;
    float mrow0 = -1e30f, mrow1 = -1e30f;
    float lrow0 = 0.f, lrow1 = 0.f;

    const int arow = warp * 16 + (lane & 15);
    const int acol = (lane >> 4) * 8;
    const int bnrow = (lane & 7) + ((lane & 16) ? 8 : 0);
    const int bkofs = (lane & 8) ? 8 : 0;
    const int vrow = lane & 15;
    const int vd = (lane >> 4) * 8;

    for (int k0 = 0; k0 < SEQ; k0 += ABN) {
        __syncthreads();
        #pragma unroll
        for (int p = 0; p < 8; p++) {
            int idx = tid + p * 128;
            int r = idx >> 4;
            int c = (idx & 15) * 8;
            size_t g = ((size_t)(b * SEQ + k0 + r)) * HDIM + c;
            int s = r * DSTR + c;
            cp16(sKh + s, Kh + g);
            cp16(sKl + s, Kl + g);
            cp16(sVh + s, Vh + g);
            cp16(sVl + s, Vl + g);
        }
        if (tid < ABN) sbias[tid] = (1.0f - mask[(size_t)b * SEQ + k0 + tid]) * -1e30f;
        cp_commit();
        cp_wait<0>();
        __syncthreads();

        // ---- S = Q K^T (bf16x3) ----
        float s[8][4];
        #pragma unroll
        for (int i = 0; i < 8; i++)
            #pragma unroll
            for (int j = 0; j < 4; j++) s[i][j] = 0.f;

        #pragma unroll
        for (int kt = 0; kt < 8; kt++) {
            uint32_t ah[4], al2[4];
            ldsm4(ah[0], ah[1], ah[2], ah[3],
                  smem_u32(sQh + arow * DSTR + kt * 16 + acol));
            ldsm4(al2[0], al2[1], al2[2], al2[3],
                  smem_u32(sQl + arow * DSTR + kt * 16 + acol));
            #pragma unroll
            for (int np = 0; np < 4; np++) {
                uint32_t bh[4];
                ldsm4(bh[0], bh[1], bh[2], bh[3],
                      smem_u32(sKh + (np * 16 + bnrow) * DSTR + kt * 16 + bkofs));
                mma_bf16(s[np * 2],     ah[0], ah[1], ah[2], ah[3], bh[0], bh[1]);
                mma_bf16(s[np * 2 + 1], ah[0], ah[1], ah[2], ah[3], bh[2], bh[3]);
                mma_bf16(s[np * 2],     al2[0], al2[1], al2[2], al2[3], bh[0], bh[1]);
                mma_bf16(s[np * 2 + 1], al2[0], al2[1], al2[2], al2[3], bh[2], bh[3]);
                uint32_t bl[4];
                ldsm4(bl[0], bl[1], bl[2], bl[3],
                      smem_u32(sKl + (np * 16 + bnrow) * DSTR + kt * 16 + bkofs));
                mma_bf16(s[np * 2],     ah[0], ah[1], ah[2], ah[3], bl[0], bl[1]);
                mma_bf16(s[np * 2 + 1], ah[0], ah[1], ah[2], ah[3], bl[2], bl[3]);
            }
        }

        // ---- online softmax (rows gid and gid+8 of this warp's 16) ----
        float mn0 = mrow0, mn1 = mrow1;
        #pragma unroll
        for (int nt = 0; nt < 8; nt++) {
            int c = nt * 8 + tig * 2;
            float b0 = sbias[c], b1 = sbias[c + 1];
            s[nt][0] = s[nt][0] * scale + b0;
            s[nt][1] = s[nt][1] * scale + b1;
            s[nt][2] = s[nt][2] * scale + b0;
            s[nt][3] = s[nt][3] * scale + b1;
            mn0 = fmaxf(mn0, fmaxf(s[nt][0], s[nt][1]));
            mn1 = fmaxf(mn1, fmaxf(s[nt][2], s[nt][3]));
        }
        mn0 = fmaxf(mn0, __shfl_xor_sync(0xffffffffu, mn0, 1));
        mn0 = fmaxf(mn0, __shfl_xor_sync(0xffffffffu, mn0, 2));
        mn1 = fmaxf(mn1, __shfl_xor_sync(0xffffffffu, mn1, 1));
        mn1 = fmaxf(mn1, __shfl_xor_sync(0xffffffffu, mn1, 2));
        float alpha0 = __expf(mrow0 - mn0);
        float alpha1 = __expf(mrow1 - mn1);
        mrow0 = mn0; mrow1 = mn1;

        float rs0 = 0.f, rs1 = 0.f;
        #pragma unroll
        for (int nt = 0; nt < 8; nt++) {
            s[nt][0] = __expf(s[nt][0] - mn0);
            s[nt][1] = __expf(s[nt][1] - mn0);
            s[nt][2] = __expf(s[nt][2] - mn1);
            s[nt][3] = __expf(s[nt][3] - mn1);
            rs0 += s[nt][0] + s[nt][1];
            rs1 += s[nt][2] + s[nt][3];
        }
        rs0 += __shfl_xor_sync(0xffffffffu, rs0, 1);
        rs0 += __shfl_xor_sync(0xffffffffu, rs0, 2);
        rs1 += __shfl_xor_sync(0xffffffffu, rs1, 1);
        rs1 += __shfl_xor_sync(0xffffffffu, rs1, 2);
        lrow0 = lrow0 * alpha0 + rs0;
        lrow1 = lrow1 * alpha1 + rs1;
        #pragma unroll
        for (int nt = 0; nt < 16; nt++) {
            o[nt][0] *= alpha0; o[nt][1] *= alpha0;
            o[nt][2] *= alpha1; o[nt][3] *= alpha1;
        }

        // ---- O += P V (bf16x3, P split in regs) ----
        #pragma unroll
        for (int t2 = 0; t2 < 4; t2++) {
            float* p0 = s[2 * t2];
            float* p1 = s[2 * t2 + 1];
            float h00 = __bfloat162float(__float2bfloat16(p0[0]));
            float h01 = __bfloat162float(__float2bfloat16(p0[1]));
            float h02 = __bfloat162float(__float2bfloat16(p0[2]));
            float h03 = __bfloat162float(__float2bfloat16(p0[3]));
            float h10 = __bfloat162float(__float2bfloat16(p1[0]));
            float h11 = __bfloat162float(__float2bfloat16(p1[1]));
            float h12 = __bfloat162float(__float2bfloat16(p1[2]));
            float h13 = __bfloat162float(__float2bfloat16(p1[3]));
            uint32_t pah[4] = { bpack(h00, h01), bpack(h02, h03), bpack(h10, h11), bpack(h12, h13) };
            uint32_t pal[4] = { bpack(p0[0] - h00, p0[1] - h01), bpack(p0[2] - h02, p0[3] - h03),
                                bpack(p1[0] - h10, p1[1] - h11), bpack(p1[2] - h12, p1[3] - h13) };
            #pragma unroll
            for (int dp = 0; dp < 8; dp++) {
                uint32_t bh[4];
                ldsm4t(bh[0], bh[1], bh[2], bh[3],
                       smem_u32(sVh + (t2 * 16 + vrow) * DSTR + dp * 16 + vd));
                mma_bf16(o[dp * 2],     pah[0], pah[1], pah[2], pah[3], bh[0], bh[1]);
                mma_bf16(o[dp * 2 + 1], pah[0], pah[1], pah[2], pah[3], bh[2], bh[3]);
                mma_bf16(o[dp * 2],     pal[0], pal[1], pal[2], pal[3], bh[0], bh[1]);
                mma_bf16(o[dp * 2 + 1], pal[0], pal[1], pal[2], pal[3], bh[2], bh[3]);
                uint32_t bl[4];
                ldsm4t(bl[0], bl[1], bl[2], bl[3],
                       smem_u32(sVl + (t2 * 16 + vrow) * DSTR + dp * 16 + vd));
                mma_bf16(o[dp * 2],     pah[0], pah[1], pah[2], pah[3], bl[0], bl[1]);
                mma_bf16(o[dp * 2 + 1], pah[0], pah[1], pah[2], pah[3], bl[2], bl[3]);
            }
        }
    }

    // ---- epilogue: normalize, split, store in [B,S,H*D] ----
    float inv0 = 1.f / lrow0;
    float inv1 = 1.f / lrow1;
    int r0 = q0 + warp * 16 + gid;
    int r1 = r0 + 8;
    #pragma unroll
    for (int nt = 0; nt < 16; nt++) {
        int c = h * HDIM + nt * 8 + tig * 2;
        size_t i0 = (size_t)(b * SEQ + r0) * HIDDEN + c;
        size_t i1 = (size_t)(b * SEQ + r1) * HIDDEN + c;
        split_store2(Oh, Ol, i0, o[nt][0] * inv0, o[nt][1] * inv0);
        split_store2(Oh, Ol, i1, o[nt][2] * inv1, o[nt][3] * inv1);
    }
}

// =================================================================
extern "C" void kernel_launch(void* const* d_in, const int* in_sizes, int n_in,
                              void* d_out, int out_size) {
    const float* hs   = (const float*)d_in[0];
    const float* mask = (const float*)d_in[1];
    const float* Wq   = (const float*)d_in[2];
    const float* Wk   = (const float*)d_in[3];
    const float* Wv   = (const float*)d_in[4];
    const float* Wo   = (const float*)d_in[5];
    float* out = (float*)d_out;

    bf16 *hsH, *hsL, *WqH, *WqL, *WkH, *WkL, *WvH, *WvL, *WoH, *WoL;
    bf16 *QH, *QL, *KH, *KL, *VH, *VL, *AH, *AL;
    cudaGetSymbolAddress((void**)&hsH, g_hsH); cudaGetSymbolAddress((void**)&hsL, g_hsL);
    cudaGetSymbolAddress((void**)&WqH, g_WqH); cudaGetSymbolAddress((void**)&WqL, g_WqL);
    cudaGetSymbolAddress((void**)&WkH, g_WkH); cudaGetSymbolAddress((void**)&WkL, g_WkL);
    cudaGetSymbolAddress((void**)&WvH, g_WvH); cudaGetSymbolAddress((void**)&WvL, g_WvL);
    cudaGetSymbolAddress((void**)&WoH, g_WoH); cudaGetSymbolAddress((void**)&WoL, g_WoL);
    cudaGetSymbolAddress((void**)&QH, g_QH);   cudaGetSymbolAddress((void**)&QL, g_QL);
    cudaGetSymbolAddress((void**)&KH, g_KH);   cudaGetSymbolAddress((void**)&KL, g_KL);
    cudaGetSymbolAddress((void**)&VH, g_VH);   cudaGetSymbolAddress((void**)&VL, g_VL);
    cudaGetSymbolAddress((void**)&AH, g_AH);   cudaGetSymbolAddress((void**)&AL, g_AL);

    cudaFuncSetAttribute(proj_all_kernel, cudaFuncAttributeMaxDynamicSharedMemorySize, GEMM_SMEM);
    cudaFuncSetAttribute(gemmO_kernel, cudaFuncAttributeMaxDynamicSharedMemorySize, GEMM_SMEM);
    cudaFuncSetAttribute(attn3_kernel, cudaFuncAttributeMaxDynamicSharedMemorySize, ATTN_SMEM);

    // fused split of all inputs into bf16 hi/lo
    split_all_kernel<<<(unsigned)((N4_ALL + 255) / 256), 256>>>(
        hs, hsH, hsL, Wq, WqH, WqL, Wk, WkH, WkL, Wv, WvH, WvL, Wo, WoH, WoL);

    // packed Q+K+V projections (KV CTAs also write broadcast fp32 cache)
    float* kout = nullptr;
    float* vout = nullptr;
    if ((size_t)out_size >= OUT_ELEMS + 2 * CACHE_ELEMS) {
        kout = out + OUT_ELEMS;
        vout = out + OUT_ELEMS + CACHE_ELEMS;
    }
    proj_all_kernel<<<576, 256, GEMM_SMEM>>>(
        hsH, hsL, WqH, WqL, QH, QL, WkH, WkL, KH, KL, WvH, WvL, VH, VL, kout, vout);

    // flash attention -> A (hi/lo)
    attn3_kernel<<<dim3(SEQ / ABM, NHEADS, BATCH), 128, ATTN_SMEM>>>(
        QH, QL, KH, KL, VH, VL, mask, AH, AL);

    // output projection -> fp32 out
    gemmO_kernel<<<dim3(HIDDEN / GBN, MTOT / GBM), 256, GEMM_SMEM>>>(
        AH, AL, WoH, WoL, out, MTOT, HIDDEN, HIDDEN);
}